// round 1
// baseline (speedup 1.0000x reference)
#include <cuda_runtime.h>
#include <cuda_bf16.h>
#include <math.h>

#define BB 32
#define NN 520
#define DEPOTN 20
#define CUSTN 500
#define EE 128
#define HH 8
#define DKK 16
#define FFHH 512
#define NLL 6
#define MM 520
#define LL 40

// ---------------- scratch (device globals; no allocation allowed) ----------------
__device__ __align__(16) float g_x   [BB*NN*EE];
__device__ __align__(16) float g_q   [BB*NN*EE];
__device__ __align__(16) float g_k   [BB*NN*EE];
__device__ __align__(16) float g_v   [BB*NN*EE];
__device__ __align__(16) float g_mh  [BB*NN*EE];
__device__ __align__(16) float g_y   [BB*NN*EE];
__device__ __align__(16) float g_x1  [BB*NN*EE];
__device__ __align__(16) float g_ffh [BB*NN*FFHH];
__device__ __align__(16) float g_part[BB*8*EE*2];
__device__ __align__(16) float g_stats[BB*EE*2];
__device__ __align__(16) float g_kd  [BB*NN*EE];
__device__ __align__(16) float g_vd  [BB*NN*EE];
__device__ __align__(16) float g_encmean[BB*EE];
__device__ __align__(16) float g_catloc [BB*MM*256];
__device__ __align__(16) float g_catrout[BB*MM*272];
__device__ __align__(16) float g_wpad[EE*272];
__device__ __align__(16) float g_qloc [BB*MM*EE];
__device__ __align__(16) float g_qrout[BB*MM*EE];
__device__ __align__(16) float g_fq   [BB*MM*EE];
__device__ __align__(16) float g_flag [BB*MM];
__device__ __align__(16) float g_attn [BB*MM*EE];
__device__ __align__(16) float g_score[BB*MM*EE];
__device__ __align__(16) float g_sn   [BB*MM*NN];

// ---------------- embedding ----------------
__global__ void embed_kernel(const float* __restrict__ dep, const float* __restrict__ cus,
                             const float* __restrict__ Wd, const float* __restrict__ bd,
                             const float* __restrict__ Wc, const float* __restrict__ bc)
{
    int idx = blockIdx.x * blockDim.x + threadIdx.x;
    if (idx >= BB*NN*EE) return;
    int e = idx % EE;
    int n = (idx / EE) % NN;
    int b = idx / (EE*NN);
    float acc;
    if (n < DEPOTN) {
        const float* f = dep + ((long)b*DEPOTN + n) * 4;
        acc = bd[e];
        #pragma unroll
        for (int j = 0; j < 4; j++) acc += f[j] * Wd[e*4 + j];
    } else {
        const float* f = cus + ((long)b*CUSTN + (n - DEPOTN)) * 3;
        acc = bc[e];
        #pragma unroll
        for (int j = 0; j < 3; j++) acc += f[j] * Wc[e*3 + j];
    }
    g_x[idx] = acc;
}

// ---------------- generic tiled GEMM: C = A @ W^T (+bias)(+resid)(+relu) ----------------
// A: (R,K) row-major, W: (Cout,K) row-major, C: (R,Cout). K must be multiple of 16.
__global__ void gemm_wt(const float* __restrict__ A, const float* __restrict__ W,
                        const float* __restrict__ bias, const float* __restrict__ resid,
                        float* __restrict__ C, int R, int K, int Cout,
                        long sA, long sW, long sC, int relu)
{
    int bz = blockIdx.z;
    A += (long)bz * sA; W += (long)bz * sW; C += (long)bz * sC;
    if (resid) resid += (long)bz * sC;

    __shared__ float As[16][65];
    __shared__ float Ws[16][65];

    int tid = threadIdx.x;
    int rowBase = blockIdx.x * 64;
    int colBase = blockIdx.y * 64;
    int t4 = tid * 4;
    int lr = t4 >> 4;            // 0..63
    int lc = t4 & 12;            // 0,4,8,12
    int tx = tid & 15, ty = tid >> 4;

    float acc[4][4];
    #pragma unroll
    for (int i = 0; i < 4; i++)
        #pragma unroll
        for (int j = 0; j < 4; j++) acc[i][j] = 0.f;

    for (int k0 = 0; k0 < K; k0 += 16) {
        int ga = rowBase + lr;
        float4 av = (ga < R) ? *(const float4*)(A + (long)ga*K + k0 + lc)
                             : make_float4(0.f,0.f,0.f,0.f);
        int gw = colBase + lr;
        float4 wv = (gw < Cout) ? *(const float4*)(W + (long)gw*K + k0 + lc)
                                : make_float4(0.f,0.f,0.f,0.f);
        __syncthreads();
        As[lc+0][lr]=av.x; As[lc+1][lr]=av.y; As[lc+2][lr]=av.z; As[lc+3][lr]=av.w;
        Ws[lc+0][lr]=wv.x; Ws[lc+1][lr]=wv.y; Ws[lc+2][lr]=wv.z; Ws[lc+3][lr]=wv.w;
        __syncthreads();
        #pragma unroll
        for (int kk = 0; kk < 16; kk++) {
            float a0 = As[kk][ty*4+0], a1 = As[kk][ty*4+1], a2 = As[kk][ty*4+2], a3 = As[kk][ty*4+3];
            float b0 = Ws[kk][tx*4+0], b1 = Ws[kk][tx*4+1], b2 = Ws[kk][tx*4+2], b3 = Ws[kk][tx*4+3];
            acc[0][0]+=a0*b0; acc[0][1]+=a0*b1; acc[0][2]+=a0*b2; acc[0][3]+=a0*b3;
            acc[1][0]+=a1*b0; acc[1][1]+=a1*b1; acc[1][2]+=a1*b2; acc[1][3]+=a1*b3;
            acc[2][0]+=a2*b0; acc[2][1]+=a2*b1; acc[2][2]+=a2*b2; acc[2][3]+=a2*b3;
            acc[3][0]+=a3*b0; acc[3][1]+=a3*b1; acc[3][2]+=a3*b2; acc[3][3]+=a3*b3;
        }
    }
    #pragma unroll
    for (int i = 0; i < 4; i++) {
        int r0 = rowBase + ty*4 + i;
        if (r0 >= R) continue;
        #pragma unroll
        for (int j = 0; j < 4; j++) {
            int c0 = colBase + tx*4 + j;
            if (c0 >= Cout) continue;
            float vv = acc[i][j];
            if (bias)  vv += bias[c0];
            if (resid) vv += resid[(long)r0*Cout + c0];
            if (relu)  vv = fmaxf(vv, 0.f);
            C[(long)r0*Cout + c0] = vv;
        }
    }
}

// ---------------- attention: one block per (query row, head, batch) ----------------
__global__ void attn_kernel(const float* __restrict__ Q, const float* __restrict__ Kt,
                            const float* __restrict__ Vt, const float* __restrict__ mask,
                            float* __restrict__ O)
{
    int qrow = blockIdx.x, h = blockIdx.y, b = blockIdx.z;
    int tid = threadIdx.x;
    __shared__ float qs[DKK];
    __shared__ float s[NN];
    __shared__ float red[128];
    __shared__ float wsum[4][DKK];

    if (tid < DKK) qs[tid] = Q[((long)(b*NN + qrow))*EE + h*DKK + tid];
    __syncthreads();

    const float* mrow = mask ? (mask + ((long)(b*MM + qrow))*NN) : (const float*)0;
    float lmax = -1e30f;
    for (int j = tid; j < NN; j += 128) {
        const float* kr = Kt + ((long)(b*NN + j))*EE + h*DKK;
        float d = 0.f;
        #pragma unroll
        for (int t = 0; t < DKK; t++) d += qs[t] * kr[t];
        d *= 0.25f;
        if (mrow) d += mrow[j];
        s[j] = d;
        lmax = fmaxf(lmax, d);
    }
    red[tid] = lmax; __syncthreads();
    for (int off = 64; off > 0; off >>= 1) {
        if (tid < off) red[tid] = fmaxf(red[tid], red[tid+off]);
        __syncthreads();
    }
    float mx = red[0]; __syncthreads();

    float lsum = 0.f;
    for (int j = tid; j < NN; j += 128) {
        float e0 = __expf(s[j] - mx);
        s[j] = e0; lsum += e0;
    }
    red[tid] = lsum; __syncthreads();
    for (int off = 64; off > 0; off >>= 1) {
        if (tid < off) red[tid] += red[tid+off];
        __syncthreads();
    }
    float inv = 1.f / red[0];

    float o[DKK];
    #pragma unroll
    for (int t = 0; t < DKK; t++) o[t] = 0.f;
    for (int j = tid; j < NN; j += 128) {
        float w = s[j] * inv;
        const float* vr = Vt + ((long)(b*NN + j))*EE + h*DKK;
        #pragma unroll
        for (int t = 0; t < DKK; t++) o[t] += w * vr[t];
    }
    #pragma unroll
    for (int off = 16; off > 0; off >>= 1)
        #pragma unroll
        for (int t = 0; t < DKK; t++) o[t] += __shfl_down_sync(0xffffffffu, o[t], off);
    int lane = tid & 31, wp = tid >> 5;
    if (lane == 0)
        #pragma unroll
        for (int t = 0; t < DKK; t++) wsum[wp][t] = o[t];
    __syncthreads();
    if (tid < DKK)
        O[((long)(b*NN + qrow))*EE + h*DKK + tid] =
            wsum[0][tid] + wsum[1][tid] + wsum[2][tid] + wsum[3][tid];
}

// ---------------- instance norm (over node axis per (b, channel)) ----------------
__global__ void inorm_stats(const float* __restrict__ Y)
{
    int b = blockIdx.x, ch = blockIdx.y, e = threadIdx.x;
    float s1 = 0.f, s2 = 0.f;
    for (int n = ch; n < NN; n += 8) {
        float v = Y[((long)(b*NN + n))*EE + e];
        s1 += v; s2 += v*v;
    }
    int idx = (b*8 + ch)*EE + e;
    g_part[idx*2]   = s1;
    g_part[idx*2+1] = s2;
}
__global__ void inorm_fin()
{
    int b = blockIdx.x, e = threadIdx.x;
    float s1 = 0.f, s2 = 0.f;
    for (int c = 0; c < 8; c++) {
        int idx = (b*8 + c)*EE + e;
        s1 += g_part[idx*2]; s2 += g_part[idx*2+1];
    }
    float mean = s1 / (float)NN;
    float var  = s2 / (float)NN - mean*mean;
    g_stats[(b*EE+e)*2]   = mean;
    g_stats[(b*EE+e)*2+1] = rsqrtf(var + 1e-5f);
}
__global__ void inorm_apply(const float* __restrict__ Y, const float* __restrict__ gg,
                            const float* __restrict__ bt, float* __restrict__ Xo)
{
    int idx = blockIdx.x * blockDim.x + threadIdx.x;
    if (idx >= BB*NN*EE) return;
    int e = idx % EE;
    int b = idx / (NN*EE);
    float mean = g_stats[(b*EE+e)*2];
    float istd = g_stats[(b*EE+e)*2+1];
    Xo[idx] = (Y[idx] - mean) * istd * gg[e] + bt[e];
}

// ---------------- decoder helpers ----------------
__global__ void encmean_kernel()
{
    int b = blockIdx.x, e = threadIdx.x;
    float s = 0.f;
    for (int n = 0; n < NN; n++) s += g_x[((long)(b*NN + n))*EE + e];
    g_encmean[b*EE + e] = s / (float)NN;
}

__global__ void build_cat(const float* __restrict__ loadv, const int* __restrict__ cur,
                          const int* __restrict__ subn, const int* __restrict__ subl,
                          const int* __restrict__ sel)
{
    int r = blockIdx.x;            // b*MM + m
    int b = r / MM;
    int e = threadIdx.x;
    int c = cur[r];
    float le = g_x[((long)(b*NN + c))*EE + e];

    int len = subl[r];
    const int* nodes = subn + (long)r*LL;
    float ssum = 0.f; int cnt = 0;
    for (int l = 0; l < LL; l++) {
        int nd = nodes[l];
        if (l < len && nd >= DEPOTN) {
            ssum += g_x[((long)(b*NN + nd))*EE + e];
            cnt++;
        }
    }
    float cntf = (cnt > 0) ? (float)cnt : 1.f;
    float smean = ssum / cntf;

    g_catloc[(long)r*256 + e]        = le;
    g_catloc[(long)r*256 + 128 + e]  = smean;
    g_catrout[(long)r*272 + e]       = le;
    g_catrout[(long)r*272 + 128 + e] = g_encmean[b*EE + e];
    if (e == 0) g_catrout[(long)r*272 + 256] = loadv[r];
    if (e >= 1 && e < 16) g_catrout[(long)r*272 + 256 + e] = 0.f;
    if (e == 0) {
        int s2 = sel[(long)r*4 + 2];
        g_flag[r] = (s2 >= DEPOTN && c < DEPOTN) ? 1.f : 0.f;
    }
}

__global__ void padw_kernel(const float* __restrict__ Wr)
{
    int idx = blockIdx.x * blockDim.x + threadIdx.x;
    if (idx >= EE*272) return;
    int rr = idx / 272, cc = idx % 272;
    g_wpad[idx] = (cc < 257) ? Wr[rr*257 + cc] : 0.f;
}

__global__ void blend_kernel()
{
    int idx = blockIdx.x * blockDim.x + threadIdx.x;
    if (idx >= BB*MM*EE) return;
    int r = idx / EE;
    float f = g_flag[r];
    g_fq[idx] = f * g_qloc[idx] + (1.f - f) * g_qrout[idx];
}

// ---------------- final tanh-clip + mask + softmax ----------------
__global__ void final_kernel(const float* __restrict__ mask, float* __restrict__ out)
{
    int r = blockIdx.x;
    int tid = threadIdx.x;
    __shared__ float buf[NN];
    __shared__ float red[256];
    const float* sn = g_sn + (long)r*NN;
    const float* mk = mask + (long)r*NN;
    const float invs = 0.08838834764831845f;  // 1/sqrt(128)

    float lm = -1e30f;
    for (int j = tid; j < NN; j += 256) {
        float v = 10.f * tanhf(sn[j] * invs) + mk[j];
        buf[j] = v;
        lm = fmaxf(lm, v);
    }
    red[tid] = lm; __syncthreads();
    for (int off = 128; off > 0; off >>= 1) {
        if (tid < off) red[tid] = fmaxf(red[tid], red[tid+off]);
        __syncthreads();
    }
    float mx = red[0]; __syncthreads();

    float ls = 0.f;
    for (int j = tid; j < NN; j += 256) {
        float e0 = __expf(buf[j] - mx);
        buf[j] = e0; ls += e0;
    }
    red[tid] = ls; __syncthreads();
    for (int off = 128; off > 0; off >>= 1) {
        if (tid < off) red[tid] += red[tid+off];
        __syncthreads();
    }
    float inv = 1.f / red[0];
    for (int j = tid; j < NN; j += 256)
        out[(long)r*NN + j] = buf[j] * inv;
}

// ---------------- host ----------------
static void launch_gemm(const float* A, const float* W, const float* bias,
                        const float* resid, float* C, int R, int K, int Cout,
                        int batch, long sA, long sW, long sC, int relu)
{
    dim3 grid((R + 63) / 64, (Cout + 63) / 64, batch);
    gemm_wt<<<grid, 256>>>(A, W, bias, resid, C, R, K, Cout, sA, sW, sC, relu);
}

extern "C" void kernel_launch(void* const* d_in, const int* in_sizes, int n_in,
                              void* d_out, int out_size)
{
    const float* depot  = (const float*)d_in[0];
    const float* cust   = (const float*)d_in[1];
    const float* mask   = (const float*)d_in[2];
    const float* loadv  = (const float*)d_in[3];
    const int*   cur    = (const int*)d_in[4];
    const int*   subn   = (const int*)d_in[5];
    const int*   subl   = (const int*)d_in[6];
    const int*   sel    = (const int*)d_in[7];
    const float* edW    = (const float*)d_in[8];
    const float* edb    = (const float*)d_in[9];
    const float* ecW    = (const float*)d_in[10];
    const float* ecb    = (const float*)d_in[11];
    const float* Wq     = (const float*)d_in[12];
    const float* Wk     = (const float*)d_in[13];
    const float* Wv     = (const float*)d_in[14];
    const float* Wc     = (const float*)d_in[15];
    const float* Wcb    = (const float*)d_in[16];
    const float* n1g    = (const float*)d_in[17];
    const float* n1b    = (const float*)d_in[18];
    const float* fW1    = (const float*)d_in[19];
    const float* fb1    = (const float*)d_in[20];
    const float* fW2    = (const float*)d_in[21];
    const float* fb2    = (const float*)d_in[22];
    const float* n2g    = (const float*)d_in[23];
    const float* n2b    = (const float*)d_in[24];
    const float* dWqloc = (const float*)d_in[25];
    const float* dWqrt  = (const float*)d_in[26];
    const float* dWk    = (const float*)d_in[27];
    const float* dWv    = (const float*)d_in[28];
    const float* dWc    = (const float*)d_in[29];
    const float* dWcb   = (const float*)d_in[30];
    float* out = (float*)d_out;

    float *px, *pq, *pk, *pv, *pmh, *py, *px1, *pffh;
    float *pkd, *pvd, *pcatloc, *pcatrout, *pwpad, *pqloc, *pqrout, *pfq, *pattn, *pscore, *psn;
    cudaGetSymbolAddress((void**)&px,   g_x);
    cudaGetSymbolAddress((void**)&pq,   g_q);
    cudaGetSymbolAddress((void**)&pk,   g_k);
    cudaGetSymbolAddress((void**)&pv,   g_v);
    cudaGetSymbolAddress((void**)&pmh,  g_mh);
    cudaGetSymbolAddress((void**)&py,   g_y);
    cudaGetSymbolAddress((void**)&px1,  g_x1);
    cudaGetSymbolAddress((void**)&pffh, g_ffh);
    cudaGetSymbolAddress((void**)&pkd,  g_kd);
    cudaGetSymbolAddress((void**)&pvd,  g_vd);
    cudaGetSymbolAddress((void**)&pcatloc,  g_catloc);
    cudaGetSymbolAddress((void**)&pcatrout, g_catrout);
    cudaGetSymbolAddress((void**)&pwpad,  g_wpad);
    cudaGetSymbolAddress((void**)&pqloc,  g_qloc);
    cudaGetSymbolAddress((void**)&pqrout, g_qrout);
    cudaGetSymbolAddress((void**)&pfq,    g_fq);
    cudaGetSymbolAddress((void**)&pattn,  g_attn);
    cudaGetSymbolAddress((void**)&pscore, g_score);
    cudaGetSymbolAddress((void**)&psn,    g_sn);

    const int R = BB * NN;                 // 16640
    const int TOT = BB * NN * EE;          // 2,129,920

    // ---- encoder embedding ----
    embed_kernel<<<(TOT + 255)/256, 256>>>(depot, cust, edW, edb, ecW, ecb);

    // ---- encoder layers ----
    for (int i = 0; i < NLL; i++) {
        launch_gemm(px, Wq + (long)i*EE*EE, 0, 0, pq, R, EE, EE, 1, 0, 0, 0, 0);
        launch_gemm(px, Wk + (long)i*EE*EE, 0, 0, pk, R, EE, EE, 1, 0, 0, 0, 0);
        launch_gemm(px, Wv + (long)i*EE*EE, 0, 0, pv, R, EE, EE, 1, 0, 0, 0, 0);
        attn_kernel<<<dim3(NN, HH, BB), 128>>>(pq, pk, pv, (const float*)0, pmh);
        launch_gemm(pmh, Wc + (long)i*EE*EE, Wcb + (long)i*EE, px, py, R, EE, EE, 1, 0, 0, 0, 0);
        inorm_stats<<<dim3(BB, 8), EE>>>(py);
        inorm_fin<<<BB, EE>>>();
        inorm_apply<<<(TOT + 255)/256, 256>>>(py, n1g + (long)i*EE, n1b + (long)i*EE, px1);
        launch_gemm(px1, fW1 + (long)i*FFHH*EE, fb1 + (long)i*FFHH, 0, pffh, R, EE, FFHH, 1, 0, 0, 0, 1);
        launch_gemm(pffh, fW2 + (long)i*EE*FFHH, fb2 + (long)i*EE, px1, py, R, FFHH, EE, 1, 0, 0, 0, 0);
        inorm_stats<<<dim3(BB, 8), EE>>>(py);
        inorm_fin<<<BB, EE>>>();
        inorm_apply<<<(TOT + 255)/256, 256>>>(py, n2g + (long)i*EE, n2b + (long)i*EE, px);
    }

    // ---- decoder ----
    launch_gemm(px, dWk, 0, 0, pkd, R, EE, EE, 1, 0, 0, 0, 0);
    launch_gemm(px, dWv, 0, 0, pvd, R, EE, EE, 1, 0, 0, 0, 0);
    encmean_kernel<<<BB, EE>>>();
    build_cat<<<BB*MM, EE>>>(loadv, cur, subn, subl, sel);
    padw_kernel<<<(EE*272 + 255)/256, 256>>>(dWqrt);
    launch_gemm(pcatloc,  dWqloc, 0, 0, pqloc,  R, 256, EE, 1, 0, 0, 0, 0);
    launch_gemm(pcatrout, pwpad,  0, 0, pqrout, R, 272, EE, 1, 0, 0, 0, 0);
    blend_kernel<<<(BB*MM*EE + 255)/256, 256>>>();
    attn_kernel<<<dim3(NN, HH, BB), 128>>>(pfq, pkd, pvd, mask, pattn);
    launch_gemm(pattn, dWc, dWcb, 0, pscore, R, EE, EE, 1, 0, 0, 0, 0);
    // score_nodes[b] = score[b] (520,128) @ encoded[b]^T (520,128)
    launch_gemm(pscore, px, 0, 0, psn, MM, EE, NN, BB,
                (long)MM*EE, (long)NN*EE, (long)MM*NN, 0);
    final_kernel<<<BB*MM, 256>>>(mask, out);
}

// round 2
// speedup vs baseline: 14.6573x; 14.6573x over previous
#include <cuda_runtime.h>
#include <cuda_bf16.h>
#include <math.h>

#define BB 32
#define NN 520
#define DEPOTN 20
#define CUSTN 500
#define EE 128
#define HH 8
#define DKK 16
#define FFHH 512
#define NLL 6
#define MM 520
#define LL 40
#define NP 524   // padded key stride in smem

// ---------------- scratch (device globals; no allocation allowed) ----------------
__device__ __align__(16) float g_x   [BB*NN*EE];
__device__ __align__(16) float g_q   [BB*NN*EE];
__device__ __align__(16) float g_k   [BB*NN*EE];
__device__ __align__(16) float g_v   [BB*NN*EE];
__device__ __align__(16) float g_mh  [BB*NN*EE];
__device__ __align__(16) float g_y   [BB*NN*EE];
__device__ __align__(16) float g_x1  [BB*NN*EE];
__device__ __align__(16) float g_ffh [BB*NN*FFHH];
__device__ __align__(16) float g_part[BB*8*EE*2];
__device__ __align__(16) float g_stats[BB*EE*2];
__device__ __align__(16) float g_kd  [BB*NN*EE];
__device__ __align__(16) float g_vd  [BB*NN*EE];
__device__ __align__(16) float g_encmean[BB*EE];
__device__ __align__(16) float g_catloc [BB*MM*256];
__device__ __align__(16) float g_catrout[BB*MM*272];
__device__ __align__(16) float g_wpad[EE*272];
__device__ __align__(16) float g_qloc [BB*MM*EE];
__device__ __align__(16) float g_qrout[BB*MM*EE];
__device__ __align__(16) float g_fq   [BB*MM*EE];
__device__ __align__(16) float g_flag [BB*MM];
__device__ __align__(16) float g_attn [BB*MM*EE];
__device__ __align__(16) float g_score[BB*MM*EE];
__device__ __align__(16) float g_sn   [BB*MM*NN];

// ---------------- embedding ----------------
__global__ void embed_kernel(const float* __restrict__ dep, const float* __restrict__ cus,
                             const float* __restrict__ Wd, const float* __restrict__ bd,
                             const float* __restrict__ Wc, const float* __restrict__ bc)
{
    int idx = blockIdx.x * blockDim.x + threadIdx.x;
    if (idx >= BB*NN*EE) return;
    int e = idx % EE;
    int n = (idx / EE) % NN;
    int b = idx / (EE*NN);
    float acc;
    if (n < DEPOTN) {
        const float* f = dep + ((long)b*DEPOTN + n) * 4;
        acc = bd[e];
        #pragma unroll
        for (int j = 0; j < 4; j++) acc += f[j] * Wd[e*4 + j];
    } else {
        const float* f = cus + ((long)b*CUSTN + (n - DEPOTN)) * 3;
        acc = bc[e];
        #pragma unroll
        for (int j = 0; j < 3; j++) acc += f[j] * Wc[e*3 + j];
    }
    g_x[idx] = acc;
}

// ---------------- generic tiled GEMM: C = A @ W^T (+bias)(+resid)(+relu) ----------------
__global__ void gemm_wt(const float* __restrict__ A, const float* __restrict__ W,
                        const float* __restrict__ bias, const float* __restrict__ resid,
                        float* __restrict__ C, int R, int K, int Cout,
                        long sA, long sW, long sC, int relu)
{
    int bz = blockIdx.z;
    A += (long)bz * sA; W += (long)bz * sW; C += (long)bz * sC;
    if (resid) resid += (long)bz * sC;

    __shared__ float As[16][65];
    __shared__ float Ws[16][65];

    int tid = threadIdx.x;
    int rowBase = blockIdx.x * 64;
    int colBase = blockIdx.y * 64;
    int t4 = tid * 4;
    int lr = t4 >> 4;
    int lc = t4 & 12;
    int tx = tid & 15, ty = tid >> 4;

    float acc[4][4];
    #pragma unroll
    for (int i = 0; i < 4; i++)
        #pragma unroll
        for (int j = 0; j < 4; j++) acc[i][j] = 0.f;

    for (int k0 = 0; k0 < K; k0 += 16) {
        int ga = rowBase + lr;
        float4 av = (ga < R) ? *(const float4*)(A + (long)ga*K + k0 + lc)
                             : make_float4(0.f,0.f,0.f,0.f);
        int gw = colBase + lr;
        float4 wv = (gw < Cout) ? *(const float4*)(W + (long)gw*K + k0 + lc)
                                : make_float4(0.f,0.f,0.f,0.f);
        __syncthreads();
        As[lc+0][lr]=av.x; As[lc+1][lr]=av.y; As[lc+2][lr]=av.z; As[lc+3][lr]=av.w;
        Ws[lc+0][lr]=wv.x; Ws[lc+1][lr]=wv.y; Ws[lc+2][lr]=wv.z; Ws[lc+3][lr]=wv.w;
        __syncthreads();
        #pragma unroll
        for (int kk = 0; kk < 16; kk++) {
            float a0 = As[kk][ty*4+0], a1 = As[kk][ty*4+1], a2 = As[kk][ty*4+2], a3 = As[kk][ty*4+3];
            float b0 = Ws[kk][tx*4+0], b1 = Ws[kk][tx*4+1], b2 = Ws[kk][tx*4+2], b3 = Ws[kk][tx*4+3];
            acc[0][0]+=a0*b0; acc[0][1]+=a0*b1; acc[0][2]+=a0*b2; acc[0][3]+=a0*b3;
            acc[1][0]+=a1*b0; acc[1][1]+=a1*b1; acc[1][2]+=a1*b2; acc[1][3]+=a1*b3;
            acc[2][0]+=a2*b0; acc[2][1]+=a2*b1; acc[2][2]+=a2*b2; acc[2][3]+=a2*b3;
            acc[3][0]+=a3*b0; acc[3][1]+=a3*b1; acc[3][2]+=a3*b2; acc[3][3]+=a3*b3;
        }
    }
    #pragma unroll
    for (int i = 0; i < 4; i++) {
        int r0 = rowBase + ty*4 + i;
        if (r0 >= R) continue;
        #pragma unroll
        for (int j = 0; j < 4; j++) {
            int c0 = colBase + tx*4 + j;
            if (c0 >= Cout) continue;
            float vv = acc[i][j];
            if (bias)  vv += bias[c0];
            if (resid) vv += resid[(long)r0*Cout + c0];
            if (relu)  vv = fmaxf(vv, 0.f);
            C[(long)r0*Cout + c0] = vv;
        }
    }
}

// ---------------- attention v2: one block per (h, b); K/V staged transposed in smem ----------------
// Each warp processes 2 queries at a time; scores live in registers.
__global__ __launch_bounds__(256, 2)
void attn2_kernel(const float* __restrict__ Q, const float* __restrict__ Kt,
                  const float* __restrict__ Vt, const float* __restrict__ mask,
                  float* __restrict__ O)
{
    int h = blockIdx.x, b = blockIdx.y;
    extern __shared__ float sm[];
    float* Ks = sm;             // [DKK][NP]
    float* Vs = sm + DKK*NP;    // [DKK][NP]

    int tid = threadIdx.x;
    const float* Kb = Kt + ((long)b*NN)*EE + h*DKK;
    const float* Vb = Vt + ((long)b*NN)*EE + h*DKK;

    // cooperative transposed load: Ks[t][n] = K[n][t]
    for (int idx = tid; idx < NN*4; idx += 256) {
        int n = idx >> 2;
        int c4 = (idx & 3) * 4;
        float4 kv = *(const float4*)(Kb + (long)n*EE + c4);
        Ks[(c4+0)*NP+n]=kv.x; Ks[(c4+1)*NP+n]=kv.y; Ks[(c4+2)*NP+n]=kv.z; Ks[(c4+3)*NP+n]=kv.w;
        float4 vv = *(const float4*)(Vb + (long)n*EE + c4);
        Vs[(c4+0)*NP+n]=vv.x; Vs[(c4+1)*NP+n]=vv.y; Vs[(c4+2)*NP+n]=vv.z; Vs[(c4+3)*NP+n]=vv.w;
    }
    __syncthreads();

    int warp = tid >> 5, lane = tid & 31;
    const unsigned FULL = 0xffffffffu;

    // 260 query pairs distributed over 8 warps
    for (int p = warp; p < NN/2; p += 8) {
        int q0 = 2*p;
        const float* Qb = Q + ((long)(b*NN + q0))*EE + h*DKK;
        float t0 = (lane < DKK) ? Qb[lane]      : 0.f;
        float t1 = (lane < DKK) ? Qb[EE + lane] : 0.f;
        float q0r[DKK], q1r[DKK];
        #pragma unroll
        for (int t = 0; t < DKK; t++) {
            q0r[t] = __shfl_sync(FULL, t0, t);
            q1r[t] = __shfl_sync(FULL, t1, t);
        }

        float s0[17], s1[17];
        float m0 = -1e30f, m1 = -1e30f;
        const float* mr0 = mask ? (mask + ((long)(b*MM + q0))*NN) : (const float*)0;
        #pragma unroll
        for (int i = 0; i < 17; i++) {
            int j = lane + 32*i;
            float a, c;
            if (j < NN) {
                a = 0.f; c = 0.f;
                #pragma unroll
                for (int t = 0; t < DKK; t++) {
                    float kv = Ks[t*NP + j];
                    a += q0r[t]*kv; c += q1r[t]*kv;
                }
                a *= 0.25f; c *= 0.25f;
                if (mr0) { a += mr0[j]; c += mr0[NN + j]; }
            } else { a = -1e30f; c = -1e30f; }
            s0[i] = a; s1[i] = c;
            m0 = fmaxf(m0, a); m1 = fmaxf(m1, c);
        }
        #pragma unroll
        for (int off = 16; off > 0; off >>= 1) {
            m0 = fmaxf(m0, __shfl_xor_sync(FULL, m0, off));
            m1 = fmaxf(m1, __shfl_xor_sync(FULL, m1, off));
        }
        float sum0 = 0.f, sum1 = 0.f;
        #pragma unroll
        for (int i = 0; i < 17; i++) {
            float e0 = __expf(s0[i] - m0);
            float e1 = __expf(s1[i] - m1);
            s0[i] = e0; s1[i] = e1;
            sum0 += e0; sum1 += e1;
        }
        #pragma unroll
        for (int off = 16; off > 0; off >>= 1) {
            sum0 += __shfl_xor_sync(FULL, sum0, off);
            sum1 += __shfl_xor_sync(FULL, sum1, off);
        }
        float inv0 = 1.f / sum0, inv1 = 1.f / sum1;

        float o0[DKK], o1[DKK];
        #pragma unroll
        for (int t = 0; t < DKK; t++) { o0[t] = 0.f; o1[t] = 0.f; }
        #pragma unroll
        for (int i = 0; i < 17; i++) {
            int j = lane + 32*i;
            if (j < NN) {
                float w0 = s0[i]*inv0, w1 = s1[i]*inv1;
                #pragma unroll
                for (int t = 0; t < DKK; t++) {
                    float vv = Vs[t*NP + j];
                    o0[t] += w0*vv; o1[t] += w1*vv;
                }
            }
        }
        #pragma unroll
        for (int t = 0; t < DKK; t++) {
            #pragma unroll
            for (int off = 16; off > 0; off >>= 1) {
                o0[t] += __shfl_xor_sync(FULL, o0[t], off);
                o1[t] += __shfl_xor_sync(FULL, o1[t], off);
            }
        }
        if (lane == 0) {
            float4* d0 = (float4*)(O + ((long)(b*NN + q0))*EE + h*DKK);
            float4* d1 = (float4*)(O + ((long)(b*NN + q0 + 1))*EE + h*DKK);
            d0[0] = make_float4(o0[0],o0[1],o0[2],o0[3]);
            d0[1] = make_float4(o0[4],o0[5],o0[6],o0[7]);
            d0[2] = make_float4(o0[8],o0[9],o0[10],o0[11]);
            d0[3] = make_float4(o0[12],o0[13],o0[14],o0[15]);
            d1[0] = make_float4(o1[0],o1[1],o1[2],o1[3]);
            d1[1] = make_float4(o1[4],o1[5],o1[6],o1[7]);
            d1[2] = make_float4(o1[8],o1[9],o1[10],o1[11]);
            d1[3] = make_float4(o1[12],o1[13],o1[14],o1[15]);
        }
    }
}

// ---------------- instance norm ----------------
__global__ void inorm_stats(const float* __restrict__ Y)
{
    int b = blockIdx.x, ch = blockIdx.y, e = threadIdx.x;
    float s1 = 0.f, s2 = 0.f;
    for (int n = ch; n < NN; n += 8) {
        float v = Y[((long)(b*NN + n))*EE + e];
        s1 += v; s2 += v*v;
    }
    int idx = (b*8 + ch)*EE + e;
    g_part[idx*2]   = s1;
    g_part[idx*2+1] = s2;
}
__global__ void inorm_fin()
{
    int b = blockIdx.x, e = threadIdx.x;
    float s1 = 0.f, s2 = 0.f;
    for (int c = 0; c < 8; c++) {
        int idx = (b*8 + c)*EE + e;
        s1 += g_part[idx*2]; s2 += g_part[idx*2+1];
    }
    float mean = s1 / (float)NN;
    float var  = s2 / (float)NN - mean*mean;
    g_stats[(b*EE+e)*2]   = mean;
    g_stats[(b*EE+e)*2+1] = rsqrtf(var + 1e-5f);
}
__global__ void inorm_apply(const float* __restrict__ Y, const float* __restrict__ gg,
                            const float* __restrict__ bt, float* __restrict__ Xo)
{
    int idx = blockIdx.x * blockDim.x + threadIdx.x;
    if (idx >= BB*NN*EE) return;
    int e = idx % EE;
    int b = idx / (NN*EE);
    float mean = g_stats[(b*EE+e)*2];
    float istd = g_stats[(b*EE+e)*2+1];
    Xo[idx] = (Y[idx] - mean) * istd * gg[e] + bt[e];
}

// ---------------- decoder helpers ----------------
__global__ void encmean_kernel()
{
    int b = blockIdx.x, e = threadIdx.x;
    float s = 0.f;
    for (int n = 0; n < NN; n++) s += g_x[((long)(b*NN + n))*EE + e];
    g_encmean[b*EE + e] = s / (float)NN;
}

__global__ void build_cat(const float* __restrict__ loadv, const int* __restrict__ cur,
                          const int* __restrict__ subn, const int* __restrict__ subl,
                          const int* __restrict__ sel)
{
    int r = blockIdx.x;
    int b = r / MM;
    int e = threadIdx.x;
    int c = cur[r];
    float le = g_x[((long)(b*NN + c))*EE + e];

    int len = subl[r];
    const int* nodes = subn + (long)r*LL;
    float ssum = 0.f; int cnt = 0;
    for (int l = 0; l < LL; l++) {
        int nd = nodes[l];
        if (l < len && nd >= DEPOTN) {
            ssum += g_x[((long)(b*NN + nd))*EE + e];
            cnt++;
        }
    }
    float cntf = (cnt > 0) ? (float)cnt : 1.f;
    float smean = ssum / cntf;

    g_catloc[(long)r*256 + e]        = le;
    g_catloc[(long)r*256 + 128 + e]  = smean;
    g_catrout[(long)r*272 + e]       = le;
    g_catrout[(long)r*272 + 128 + e] = g_encmean[b*EE + e];
    if (e == 0) g_catrout[(long)r*272 + 256] = loadv[r];
    if (e >= 1 && e < 16) g_catrout[(long)r*272 + 256 + e] = 0.f;
    if (e == 0) {
        int s2 = sel[(long)r*4 + 2];
        g_flag[r] = (s2 >= DEPOTN && c < DEPOTN) ? 1.f : 0.f;
    }
}

__global__ void padw_kernel(const float* __restrict__ Wr)
{
    int idx = blockIdx.x * blockDim.x + threadIdx.x;
    if (idx >= EE*272) return;
    int rr = idx / 272, cc = idx % 272;
    g_wpad[idx] = (cc < 257) ? Wr[rr*257 + cc] : 0.f;
}

__global__ void blend_kernel()
{
    int idx = blockIdx.x * blockDim.x + threadIdx.x;
    if (idx >= BB*MM*EE) return;
    int r = idx / EE;
    float f = g_flag[r];
    g_fq[idx] = f * g_qloc[idx] + (1.f - f) * g_qrout[idx];
}

// ---------------- final tanh-clip + mask + softmax ----------------
__global__ void final_kernel(const float* __restrict__ mask, float* __restrict__ out)
{
    int r = blockIdx.x;
    int tid = threadIdx.x;
    __shared__ float buf[NN];
    __shared__ float red[256];
    const float* sn = g_sn + (long)r*NN;
    const float* mk = mask + (long)r*NN;
    const float invs = 0.08838834764831845f;

    float lm = -1e30f;
    for (int j = tid; j < NN; j += 256) {
        float v = 10.f * tanhf(sn[j] * invs) + mk[j];
        buf[j] = v;
        lm = fmaxf(lm, v);
    }
    red[tid] = lm; __syncthreads();
    for (int off = 128; off > 0; off >>= 1) {
        if (tid < off) red[tid] = fmaxf(red[tid], red[tid+off]);
        __syncthreads();
    }
    float mx = red[0]; __syncthreads();

    float ls = 0.f;
    for (int j = tid; j < NN; j += 256) {
        float e0 = __expf(buf[j] - mx);
        buf[j] = e0; ls += e0;
    }
    red[tid] = ls; __syncthreads();
    for (int off = 128; off > 0; off >>= 1) {
        if (tid < off) red[tid] += red[tid+off];
        __syncthreads();
    }
    float inv = 1.f / red[0];
    for (int j = tid; j < NN; j += 256)
        out[(long)r*NN + j] = buf[j] * inv;
}

// ---------------- host ----------------
static void launch_gemm(const float* A, const float* W, const float* bias,
                        const float* resid, float* C, int R, int K, int Cout,
                        int batch, long sA, long sW, long sC, int relu)
{
    dim3 grid((R + 63) / 64, (Cout + 63) / 64, batch);
    gemm_wt<<<grid, 256>>>(A, W, bias, resid, C, R, K, Cout, sA, sW, sC, relu);
}

extern "C" void kernel_launch(void* const* d_in, const int* in_sizes, int n_in,
                              void* d_out, int out_size)
{
    const float* depot  = (const float*)d_in[0];
    const float* cust   = (const float*)d_in[1];
    const float* mask   = (const float*)d_in[2];
    const float* loadv  = (const float*)d_in[3];
    const int*   cur    = (const int*)d_in[4];
    const int*   subn   = (const int*)d_in[5];
    const int*   subl   = (const int*)d_in[6];
    const int*   sel    = (const int*)d_in[7];
    const float* edW    = (const float*)d_in[8];
    const float* edb    = (const float*)d_in[9];
    const float* ecW    = (const float*)d_in[10];
    const float* ecb    = (const float*)d_in[11];
    const float* Wq     = (const float*)d_in[12];
    const float* Wk     = (const float*)d_in[13];
    const float* Wv     = (const float*)d_in[14];
    const float* Wc     = (const float*)d_in[15];
    const float* Wcb    = (const float*)d_in[16];
    const float* n1g    = (const float*)d_in[17];
    const float* n1b    = (const float*)d_in[18];
    const float* fW1    = (const float*)d_in[19];
    const float* fb1    = (const float*)d_in[20];
    const float* fW2    = (const float*)d_in[21];
    const float* fb2    = (const float*)d_in[22];
    const float* n2g    = (const float*)d_in[23];
    const float* n2b    = (const float*)d_in[24];
    const float* dWqloc = (const float*)d_in[25];
    const float* dWqrt  = (const float*)d_in[26];
    const float* dWk    = (const float*)d_in[27];
    const float* dWv    = (const float*)d_in[28];
    const float* dWc    = (const float*)d_in[29];
    const float* dWcb   = (const float*)d_in[30];
    float* out = (float*)d_out;

    float *px, *pq, *pk, *pv, *pmh, *py, *px1, *pffh;
    float *pkd, *pvd, *pcatloc, *pcatrout, *pwpad, *pqloc, *pqrout, *pfq, *pattn, *pscore, *psn;
    cudaGetSymbolAddress((void**)&px,   g_x);
    cudaGetSymbolAddress((void**)&pq,   g_q);
    cudaGetSymbolAddress((void**)&pk,   g_k);
    cudaGetSymbolAddress((void**)&pv,   g_v);
    cudaGetSymbolAddress((void**)&pmh,  g_mh);
    cudaGetSymbolAddress((void**)&py,   g_y);
    cudaGetSymbolAddress((void**)&px1,  g_x1);
    cudaGetSymbolAddress((void**)&pffh, g_ffh);
    cudaGetSymbolAddress((void**)&pkd,  g_kd);
    cudaGetSymbolAddress((void**)&pvd,  g_vd);
    cudaGetSymbolAddress((void**)&pcatloc,  g_catloc);
    cudaGetSymbolAddress((void**)&pcatrout, g_catrout);
    cudaGetSymbolAddress((void**)&pwpad,  g_wpad);
    cudaGetSymbolAddress((void**)&pqloc,  g_qloc);
    cudaGetSymbolAddress((void**)&pqrout, g_qrout);
    cudaGetSymbolAddress((void**)&pfq,    g_fq);
    cudaGetSymbolAddress((void**)&pattn,  g_attn);
    cudaGetSymbolAddress((void**)&pscore, g_score);
    cudaGetSymbolAddress((void**)&psn,    g_sn);

    const int R = BB * NN;
    const int TOT = BB * NN * EE;
    const int ATTN_SMEM = 2 * DKK * NP * (int)sizeof(float);  // 67,072 B
    static int smem_set = 0;
    if (!smem_set) {
        cudaFuncSetAttribute(attn2_kernel, cudaFuncAttributeMaxDynamicSharedMemorySize, ATTN_SMEM);
        smem_set = 1;
    }

    embed_kernel<<<(TOT + 255)/256, 256>>>(depot, cust, edW, edb, ecW, ecb);

    for (int i = 0; i < NLL; i++) {
        launch_gemm(px, Wq + (long)i*EE*EE, 0, 0, pq, R, EE, EE, 1, 0, 0, 0, 0);
        launch_gemm(px, Wk + (long)i*EE*EE, 0, 0, pk, R, EE, EE, 1, 0, 0, 0, 0);
        launch_gemm(px, Wv + (long)i*EE*EE, 0, 0, pv, R, EE, EE, 1, 0, 0, 0, 0);
        attn2_kernel<<<dim3(HH, BB), 256, ATTN_SMEM>>>(pq, pk, pv, (const float*)0, pmh);
        launch_gemm(pmh, Wc + (long)i*EE*EE, Wcb + (long)i*EE, px, py, R, EE, EE, 1, 0, 0, 0, 0);
        inorm_stats<<<dim3(BB, 8), EE>>>(py);
        inorm_fin<<<BB, EE>>>();
        inorm_apply<<<(TOT + 255)/256, 256>>>(py, n1g + (long)i*EE, n1b + (long)i*EE, px1);
        launch_gemm(px1, fW1 + (long)i*FFHH*EE, fb1 + (long)i*FFHH, 0, pffh, R, EE, FFHH, 1, 0, 0, 0, 1);
        launch_gemm(pffh, fW2 + (long)i*EE*FFHH, fb2 + (long)i*EE, px1, py, R, FFHH, EE, 1, 0, 0, 0, 0);
        inorm_stats<<<dim3(BB, 8), EE>>>(py);
        inorm_fin<<<BB, EE>>>();
        inorm_apply<<<(TOT + 255)/256, 256>>>(py, n2g + (long)i*EE, n2b + (long)i*EE, px);
    }

    launch_gemm(px, dWk, 0, 0, pkd, R, EE, EE, 1, 0, 0, 0, 0);
    launch_gemm(px, dWv, 0, 0, pvd, R, EE, EE, 1, 0, 0, 0, 0);
    encmean_kernel<<<BB, EE>>>();
    build_cat<<<BB*MM, EE>>>(loadv, cur, subn, subl, sel);
    padw_kernel<<<(EE*272 + 255)/256, 256>>>(dWqrt);
    launch_gemm(pcatloc,  dWqloc, 0, 0, pqloc,  R, 256, EE, 1, 0, 0, 0, 0);
    launch_gemm(pcatrout, pwpad,  0, 0, pqrout, R, 272, EE, 1, 0, 0, 0, 0);
    blend_kernel<<<(BB*MM*EE + 255)/256, 256>>>();
    attn2_kernel<<<dim3(HH, BB), 256, ATTN_SMEM>>>(pfq, pkd, pvd, mask, pattn);
    launch_gemm(pattn, dWc, dWcb, 0, pscore, R, EE, EE, 1, 0, 0, 0, 0);
    launch_gemm(pscore, px, 0, 0, psn, MM, EE, NN, BB,
                (long)MM*EE, (long)NN*EE, (long)MM*NN, 0);
    final_kernel<<<BB*MM, 256>>>(mask, out);
}

// round 3
// speedup vs baseline: 16.9079x; 1.1536x over previous
#include <cuda_runtime.h>
#include <cuda_bf16.h>
#include <math.h>

#define BB 32
#define NN 520
#define DEPOTN 20
#define CUSTN 500
#define EE 128
#define HH 8
#define DKK 16
#define FFHH 512
#define NLL 6
#define MM 520
#define LL 40
#define NP 524   // padded key stride in smem

// ---------------- scratch ----------------
__device__ __align__(16) float g_x   [BB*NN*EE];
__device__ __align__(16) float g_q   [BB*NN*EE];
__device__ __align__(16) float g_k   [BB*NN*EE];
__device__ __align__(16) float g_v   [BB*NN*EE];
__device__ __align__(16) float g_mh  [BB*NN*EE];
__device__ __align__(16) float g_y   [BB*NN*EE];
__device__ __align__(16) float g_x1  [BB*NN*EE];
__device__ __align__(16) float g_ffh [BB*NN*FFHH];
__device__ __align__(16) float g_part[BB*8*EE*2];
__device__ __align__(16) float g_stats[BB*EE*2];
__device__ __align__(16) float g_kd  [BB*NN*EE];
__device__ __align__(16) float g_vd  [BB*NN*EE];
__device__ __align__(16) float g_encmean[BB*EE];
__device__ __align__(16) float g_catloc [BB*MM*256];
__device__ __align__(16) float g_catrout[BB*MM*272];
__device__ __align__(16) float g_wpad[EE*272];
__device__ __align__(16) float g_qloc [BB*MM*EE];
__device__ __align__(16) float g_qrout[BB*MM*EE];
__device__ __align__(16) float g_fq   [BB*MM*EE];
__device__ __align__(16) float g_flag [BB*MM];
__device__ __align__(16) float g_attn [BB*MM*EE];
__device__ __align__(16) float g_score[BB*MM*EE];
__device__ __align__(16) float g_sn   [BB*MM*NN];

// ---------------- embedding ----------------
__global__ void embed_kernel(const float* __restrict__ dep, const float* __restrict__ cus,
                             const float* __restrict__ Wd, const float* __restrict__ bd,
                             const float* __restrict__ Wc, const float* __restrict__ bc)
{
    int idx = blockIdx.x * blockDim.x + threadIdx.x;
    if (idx >= BB*NN*EE) return;
    int e = idx % EE;
    int n = (idx / EE) % NN;
    int b = idx / (EE*NN);
    float acc;
    if (n < DEPOTN) {
        const float* f = dep + ((long)b*DEPOTN + n) * 4;
        acc = bd[e];
        #pragma unroll
        for (int j = 0; j < 4; j++) acc += f[j] * Wd[e*4 + j];
    } else {
        const float* f = cus + ((long)b*CUSTN + (n - DEPOTN)) * 3;
        acc = bc[e];
        #pragma unroll
        for (int j = 0; j < 3; j++) acc += f[j] * Wc[e*3 + j];
    }
    g_x[idx] = acc;
}

// ---------------- GEMM v2: 128x128 tile, 8x8 micro-tile ----------------
// C = A @ W^T (+bias)(+resid)(+relu). A:(R,K), W:(Cout,K), C:(R,Cout). K%16==0, Cout%4==0.
__global__ __launch_bounds__(256, 2)
void gemm_v2(const float* __restrict__ A, const float* __restrict__ W,
             const float* __restrict__ bias, const float* __restrict__ resid,
             float* __restrict__ C, int R, int K, int Cout,
             long sA, long sW, long sC, int relu)
{
    int bz = blockIdx.z;
    A += (long)bz * sA; W += (long)bz * sW; C += (long)bz * sC;
    if (resid) resid += (long)bz * sC;

    __shared__ float As[16][128];
    __shared__ float Bs[16][128];

    int tid = threadIdx.x;
    int tx = tid & 15, ty = tid >> 4;
    int rowBase = blockIdx.x * 128;
    int colBase = blockIdx.y * 128;

    float acc[8][8];
    #pragma unroll
    for (int i = 0; i < 8; i++)
        #pragma unroll
        for (int j = 0; j < 8; j++) acc[i][j] = 0.f;

    for (int k0 = 0; k0 < K; k0 += 16) {
        __syncthreads();
        #pragma unroll
        for (int ss = 0; ss < 2; ss++) {
            int s = tid + ss*256;
            int row = s >> 2;
            int kq = (s & 3) * 4;
            int ga = rowBase + row;
            float4 av = (ga < R) ? *(const float4*)(A + (long)ga*K + k0 + kq)
                                 : make_float4(0.f,0.f,0.f,0.f);
            As[kq+0][row]=av.x; As[kq+1][row]=av.y; As[kq+2][row]=av.z; As[kq+3][row]=av.w;
            int gw = colBase + row;
            float4 wv = (gw < Cout) ? *(const float4*)(W + (long)gw*K + k0 + kq)
                                    : make_float4(0.f,0.f,0.f,0.f);
            Bs[kq+0][row]=wv.x; Bs[kq+1][row]=wv.y; Bs[kq+2][row]=wv.z; Bs[kq+3][row]=wv.w;
        }
        __syncthreads();
        #pragma unroll
        for (int kk = 0; kk < 16; kk++) {
            float a[8], b[8];
            *(float4*)&a[0] = *(const float4*)&As[kk][ty*4];
            *(float4*)&a[4] = *(const float4*)&As[kk][64 + ty*4];
            *(float4*)&b[0] = *(const float4*)&Bs[kk][tx*4];
            *(float4*)&b[4] = *(const float4*)&Bs[kk][64 + tx*4];
            #pragma unroll
            for (int i = 0; i < 8; i++)
                #pragma unroll
                for (int j = 0; j < 8; j++)
                    acc[i][j] += a[i] * b[j];
        }
    }

    #pragma unroll
    for (int i = 0; i < 8; i++) {
        int r0 = rowBase + ((i < 4) ? (ty*4 + i) : (64 + ty*4 + i - 4));
        if (r0 >= R) continue;
        #pragma unroll
        for (int jh = 0; jh < 2; jh++) {
            int c0 = colBase + ((jh == 0) ? (tx*4) : (64 + tx*4));
            if (c0 + 3 >= Cout) continue;
            float4 vv;
            vv.x = acc[i][jh*4+0]; vv.y = acc[i][jh*4+1];
            vv.z = acc[i][jh*4+2]; vv.w = acc[i][jh*4+3];
            if (bias) {
                vv.x += bias[c0+0]; vv.y += bias[c0+1];
                vv.z += bias[c0+2]; vv.w += bias[c0+3];
            }
            if (resid) {
                float4 rv = *(const float4*)(resid + (long)r0*Cout + c0);
                vv.x += rv.x; vv.y += rv.y; vv.z += rv.z; vv.w += rv.w;
            }
            if (relu) {
                vv.x = fmaxf(vv.x, 0.f); vv.y = fmaxf(vv.y, 0.f);
                vv.z = fmaxf(vv.z, 0.f); vv.w = fmaxf(vv.w, 0.f);
            }
            *(float4*)(C + (long)r0*Cout + c0) = vv;
        }
    }
}

// ---------------- attention v3: 4 queries per warp pass; dk split halves ----------------
__global__ __launch_bounds__(256, 2)
void attn3_kernel(const float* __restrict__ Q, const float* __restrict__ Kt,
                  const float* __restrict__ Vt, const float* __restrict__ mask,
                  float* __restrict__ O)
{
    int h = blockIdx.x, b = blockIdx.y;
    extern __shared__ float sm[];
    float* Ks = sm;
    float* Vs = sm + DKK*NP;

    int tid = threadIdx.x;
    const float* Kb = Kt + ((long)b*NN)*EE + h*DKK;
    const float* Vb = Vt + ((long)b*NN)*EE + h*DKK;

    for (int idx = tid; idx < NN*4; idx += 256) {
        int n = idx >> 2;
        int c4 = (idx & 3) * 4;
        float4 kv = *(const float4*)(Kb + (long)n*EE + c4);
        Ks[(c4+0)*NP+n]=kv.x; Ks[(c4+1)*NP+n]=kv.y; Ks[(c4+2)*NP+n]=kv.z; Ks[(c4+3)*NP+n]=kv.w;
        float4 vv = *(const float4*)(Vb + (long)n*EE + c4);
        Vs[(c4+0)*NP+n]=vv.x; Vs[(c4+1)*NP+n]=vv.y; Vs[(c4+2)*NP+n]=vv.z; Vs[(c4+3)*NP+n]=vv.w;
    }
    __syncthreads();

    int warp = tid >> 5, lane = tid & 31;
    const unsigned FULL = 0xffffffffu;

    for (int p = warp; p < NN/4; p += 8) {       // 130 groups of 4 queries
        int q0 = 4*p;
        const float* Qb = Q + ((long)(b*NN + q0))*EE + h*DKK;
        const float* mr = mask ? (mask + ((long)(b*MM + q0))*NN) : (const float*)0;

        float s0[17], s1[17], s2[17], s3[17];
        #pragma unroll
        for (int i = 0; i < 17; i++) { s0[i]=0.f; s1[i]=0.f; s2[i]=0.f; s3[i]=0.f; }

        // QK^T accumulated in two dk-halves (limits live registers)
        #pragma unroll
        for (int th = 0; th < 2; th++) {
            float qr0[8], qr1[8], qr2[8], qr3[8];
            {
                float t0 = (lane < 8) ? Qb[0*EE + th*8 + lane] : 0.f;
                float t1 = (lane < 8) ? Qb[1*EE + th*8 + lane] : 0.f;
                float t2 = (lane < 8) ? Qb[2*EE + th*8 + lane] : 0.f;
                float t3 = (lane < 8) ? Qb[3*EE + th*8 + lane] : 0.f;
                #pragma unroll
                for (int t = 0; t < 8; t++) {
                    qr0[t] = __shfl_sync(FULL, t0, t);
                    qr1[t] = __shfl_sync(FULL, t1, t);
                    qr2[t] = __shfl_sync(FULL, t2, t);
                    qr3[t] = __shfl_sync(FULL, t3, t);
                }
            }
            #pragma unroll
            for (int i = 0; i < 17; i++) {
                int j = lane + 32*i;
                if (j < NN) {
                    float a0=0.f, a1=0.f, a2=0.f, a3=0.f;
                    #pragma unroll
                    for (int t = 0; t < 8; t++) {
                        float kv = Ks[(th*8 + t)*NP + j];
                        a0 += qr0[t]*kv; a1 += qr1[t]*kv;
                        a2 += qr2[t]*kv; a3 += qr3[t]*kv;
                    }
                    s0[i] += a0; s1[i] += a1; s2[i] += a2; s3[i] += a3;
                }
            }
        }

        float m0=-1e30f, m1=-1e30f, m2=-1e30f, m3=-1e30f;
        #pragma unroll
        for (int i = 0; i < 17; i++) {
            int j = lane + 32*i;
            if (j < NN) {
                float a0 = s0[i]*0.25f, a1 = s1[i]*0.25f, a2 = s2[i]*0.25f, a3 = s3[i]*0.25f;
                if (mr) {
                    a0 += mr[j]; a1 += mr[NN + j]; a2 += mr[2*NN + j]; a3 += mr[3*NN + j];
                }
                s0[i]=a0; s1[i]=a1; s2[i]=a2; s3[i]=a3;
                m0=fmaxf(m0,a0); m1=fmaxf(m1,a1); m2=fmaxf(m2,a2); m3=fmaxf(m3,a3);
            } else {
                s0[i]=-1e30f; s1[i]=-1e30f; s2[i]=-1e30f; s3[i]=-1e30f;
            }
        }
        #pragma unroll
        for (int off = 16; off > 0; off >>= 1) {
            m0 = fmaxf(m0, __shfl_xor_sync(FULL, m0, off));
            m1 = fmaxf(m1, __shfl_xor_sync(FULL, m1, off));
            m2 = fmaxf(m2, __shfl_xor_sync(FULL, m2, off));
            m3 = fmaxf(m3, __shfl_xor_sync(FULL, m3, off));
        }
        float u0=0.f, u1=0.f, u2=0.f, u3=0.f;
        #pragma unroll
        for (int i = 0; i < 17; i++) {
            float e0=__expf(s0[i]-m0), e1=__expf(s1[i]-m1);
            float e2=__expf(s2[i]-m2), e3=__expf(s3[i]-m3);
            s0[i]=e0; s1[i]=e1; s2[i]=e2; s3[i]=e3;
            u0+=e0; u1+=e1; u2+=e2; u3+=e3;
        }
        #pragma unroll
        for (int off = 16; off > 0; off >>= 1) {
            u0 += __shfl_xor_sync(FULL, u0, off);
            u1 += __shfl_xor_sync(FULL, u1, off);
            u2 += __shfl_xor_sync(FULL, u2, off);
            u3 += __shfl_xor_sync(FULL, u3, off);
        }
        float i0=1.f/u0, i1=1.f/u1, i2=1.f/u2, i3=1.f/u3;

        // PV in two dk-halves
        #pragma unroll
        for (int th = 0; th < 2; th++) {
            float o0[8], o1[8], o2[8], o3[8];
            #pragma unroll
            for (int t = 0; t < 8; t++) { o0[t]=0.f; o1[t]=0.f; o2[t]=0.f; o3[t]=0.f; }
            #pragma unroll
            for (int i = 0; i < 17; i++) {
                int j = lane + 32*i;
                if (j < NN) {
                    float w0=s0[i]*i0, w1=s1[i]*i1, w2=s2[i]*i2, w3=s3[i]*i3;
                    #pragma unroll
                    for (int t = 0; t < 8; t++) {
                        float vv = Vs[(th*8 + t)*NP + j];
                        o0[t]+=w0*vv; o1[t]+=w1*vv; o2[t]+=w2*vv; o3[t]+=w3*vv;
                    }
                }
            }
            #pragma unroll
            for (int t = 0; t < 8; t++) {
                #pragma unroll
                for (int off = 16; off > 0; off >>= 1) {
                    o0[t] += __shfl_xor_sync(FULL, o0[t], off);
                    o1[t] += __shfl_xor_sync(FULL, o1[t], off);
                    o2[t] += __shfl_xor_sync(FULL, o2[t], off);
                    o3[t] += __shfl_xor_sync(FULL, o3[t], off);
                }
            }
            if (lane == 0) {
                float* d = O + ((long)(b*NN + q0))*EE + h*DKK + th*8;
                ((float4*)d)[0]          = make_float4(o0[0],o0[1],o0[2],o0[3]);
                ((float4*)d)[1]          = make_float4(o0[4],o0[5],o0[6],o0[7]);
                ((float4*)(d+EE))[0]     = make_float4(o1[0],o1[1],o1[2],o1[3]);
                ((float4*)(d+EE))[1]     = make_float4(o1[4],o1[5],o1[6],o1[7]);
                ((float4*)(d+2*EE))[0]   = make_float4(o2[0],o2[1],o2[2],o2[3]);
                ((float4*)(d+2*EE))[1]   = make_float4(o2[4],o2[5],o2[6],o2[7]);
                ((float4*)(d+3*EE))[0]   = make_float4(o3[0],o3[1],o3[2],o3[3]);
                ((float4*)(d+3*EE))[1]   = make_float4(o3[4],o3[5],o3[6],o3[7]);
            }
        }
    }
}

// ---------------- instance norm ----------------
__global__ void inorm_stats(const float* __restrict__ Y)
{
    int b = blockIdx.x, ch = blockIdx.y, e = threadIdx.x;
    float s1 = 0.f, s2 = 0.f;
    for (int n = ch; n < NN; n += 8) {
        float v = Y[((long)(b*NN + n))*EE + e];
        s1 += v; s2 += v*v;
    }
    int idx = (b*8 + ch)*EE + e;
    g_part[idx*2]   = s1;
    g_part[idx*2+1] = s2;
}
__global__ void inorm_fin()
{
    int b = blockIdx.x, e = threadIdx.x;
    float s1 = 0.f, s2 = 0.f;
    for (int c = 0; c < 8; c++) {
        int idx = (b*8 + c)*EE + e;
        s1 += g_part[idx*2]; s2 += g_part[idx*2+1];
    }
    float mean = s1 / (float)NN;
    float var  = s2 / (float)NN - mean*mean;
    g_stats[(b*EE+e)*2]   = mean;
    g_stats[(b*EE+e)*2+1] = rsqrtf(var + 1e-5f);
}
__global__ void inorm_apply(const float* __restrict__ Y, const float* __restrict__ gg,
                            const float* __restrict__ bt, float* __restrict__ Xo)
{
    int idx = blockIdx.x * blockDim.x + threadIdx.x;
    if (idx >= BB*NN*EE) return;
    int e = idx % EE;
    int b = idx / (NN*EE);
    float mean = g_stats[(b*EE+e)*2];
    float istd = g_stats[(b*EE+e)*2+1];
    Xo[idx] = (Y[idx] - mean) * istd * gg[e] + bt[e];
}

// ---------------- decoder helpers ----------------
__global__ void encmean_kernel()
{
    int b = blockIdx.x, e = threadIdx.x;
    float s = 0.f;
    for (int n = 0; n < NN; n++) s += g_x[((long)(b*NN + n))*EE + e];
    g_encmean[b*EE + e] = s / (float)NN;
}

__global__ void build_cat(const float* __restrict__ loadv, const int* __restrict__ cur,
                          const int* __restrict__ subn, const int* __restrict__ subl,
                          const int* __restrict__ sel)
{
    int r = blockIdx.x;
    int b = r / MM;
    int e = threadIdx.x;
    int c = cur[r];
    float le = g_x[((long)(b*NN + c))*EE + e];

    int len = subl[r];
    const int* nodes = subn + (long)r*LL;
    float ssum = 0.f; int cnt = 0;
    for (int l = 0; l < LL; l++) {
        int nd = nodes[l];
        if (l < len && nd >= DEPOTN) {
            ssum += g_x[((long)(b*NN + nd))*EE + e];
            cnt++;
        }
    }
    float cntf = (cnt > 0) ? (float)cnt : 1.f;
    float smean = ssum / cntf;

    g_catloc[(long)r*256 + e]        = le;
    g_catloc[(long)r*256 + 128 + e]  = smean;
    g_catrout[(long)r*272 + e]       = le;
    g_catrout[(long)r*272 + 128 + e] = g_encmean[b*EE + e];
    if (e == 0) g_catrout[(long)r*272 + 256] = loadv[r];
    if (e >= 1 && e < 16) g_catrout[(long)r*272 + 256 + e] = 0.f;
    if (e == 0) {
        int s2 = sel[(long)r*4 + 2];
        g_flag[r] = (s2 >= DEPOTN && c < DEPOTN) ? 1.f : 0.f;
    }
}

__global__ void padw_kernel(const float* __restrict__ Wr)
{
    int idx = blockIdx.x * blockDim.x + threadIdx.x;
    if (idx >= EE*272) return;
    int rr = idx / 272, cc = idx % 272;
    g_wpad[idx] = (cc < 257) ? Wr[rr*257 + cc] : 0.f;
}

__global__ void blend_kernel()
{
    int idx = blockIdx.x * blockDim.x + threadIdx.x;
    if (idx >= BB*MM*EE) return;
    int r = idx / EE;
    float f = g_flag[r];
    g_fq[idx] = f * g_qloc[idx] + (1.f - f) * g_qrout[idx];
}

// ---------------- final tanh-clip + mask + softmax ----------------
__global__ void final_kernel(const float* __restrict__ mask, float* __restrict__ out)
{
    int r = blockIdx.x;
    int tid = threadIdx.x;
    __shared__ float buf[NN];
    __shared__ float red[256];
    const float* sn = g_sn + (long)r*NN;
    const float* mk = mask + (long)r*NN;
    const float invs = 0.08838834764831845f;

    float lm = -1e30f;
    for (int j = tid; j < NN; j += 256) {
        float v = 10.f * tanhf(sn[j] * invs) + mk[j];
        buf[j] = v;
        lm = fmaxf(lm, v);
    }
    red[tid] = lm; __syncthreads();
    for (int off = 128; off > 0; off >>= 1) {
        if (tid < off) red[tid] = fmaxf(red[tid], red[tid+off]);
        __syncthreads();
    }
    float mx = red[0]; __syncthreads();

    float ls = 0.f;
    for (int j = tid; j < NN; j += 256) {
        float e0 = __expf(buf[j] - mx);
        buf[j] = e0; ls += e0;
    }
    red[tid] = ls; __syncthreads();
    for (int off = 128; off > 0; off >>= 1) {
        if (tid < off) red[tid] += red[tid+off];
        __syncthreads();
    }
    float inv = 1.f / red[0];
    for (int j = tid; j < NN; j += 256)
        out[(long)r*NN + j] = buf[j] * inv;
}

// ---------------- host ----------------
static void launch_gemm(const float* A, const float* W, const float* bias,
                        const float* resid, float* C, int R, int K, int Cout,
                        int batch, long sA, long sW, long sC, int relu)
{
    dim3 grid((R + 127) / 128, (Cout + 127) / 128, batch);
    gemm_v2<<<grid, 256>>>(A, W, bias, resid, C, R, K, Cout, sA, sW, sC, relu);
}

extern "C" void kernel_launch(void* const* d_in, const int* in_sizes, int n_in,
                              void* d_out, int out_size)
{
    const float* depot  = (const float*)d_in[0];
    const float* cust   = (const float*)d_in[1];
    const float* mask   = (const float*)d_in[2];
    const float* loadv  = (const float*)d_in[3];
    const int*   cur    = (const int*)d_in[4];
    const int*   subn   = (const int*)d_in[5];
    const int*   subl   = (const int*)d_in[6];
    const int*   sel    = (const int*)d_in[7];
    const float* edW    = (const float*)d_in[8];
    const float* edb    = (const float*)d_in[9];
    const float* ecW    = (const float*)d_in[10];
    const float* ecb    = (const float*)d_in[11];
    const float* Wq     = (const float*)d_in[12];
    const float* Wk     = (const float*)d_in[13];
    const float* Wv     = (const float*)d_in[14];
    const float* Wc     = (const float*)d_in[15];
    const float* Wcb    = (const float*)d_in[16];
    const float* n1g    = (const float*)d_in[17];
    const float* n1b    = (const float*)d_in[18];
    const float* fW1    = (const float*)d_in[19];
    const float* fb1    = (const float*)d_in[20];
    const float* fW2    = (const float*)d_in[21];
    const float* fb2    = (const float*)d_in[22];
    const float* n2g    = (const float*)d_in[23];
    const float* n2b    = (const float*)d_in[24];
    const float* dWqloc = (const float*)d_in[25];
    const float* dWqrt  = (const float*)d_in[26];
    const float* dWk    = (const float*)d_in[27];
    const float* dWv    = (const float*)d_in[28];
    const float* dWc    = (const float*)d_in[29];
    const float* dWcb   = (const float*)d_in[30];
    float* out = (float*)d_out;

    float *px, *pq, *pk, *pv, *pmh, *py, *px1, *pffh;
    float *pkd, *pvd, *pcatloc, *pcatrout, *pwpad, *pqloc, *pqrout, *pfq, *pattn, *pscore, *psn;
    cudaGetSymbolAddress((void**)&px,   g_x);
    cudaGetSymbolAddress((void**)&pq,   g_q);
    cudaGetSymbolAddress((void**)&pk,   g_k);
    cudaGetSymbolAddress((void**)&pv,   g_v);
    cudaGetSymbolAddress((void**)&pmh,  g_mh);
    cudaGetSymbolAddress((void**)&py,   g_y);
    cudaGetSymbolAddress((void**)&px1,  g_x1);
    cudaGetSymbolAddress((void**)&pffh, g_ffh);
    cudaGetSymbolAddress((void**)&pkd,  g_kd);
    cudaGetSymbolAddress((void**)&pvd,  g_vd);
    cudaGetSymbolAddress((void**)&pcatloc,  g_catloc);
    cudaGetSymbolAddress((void**)&pcatrout, g_catrout);
    cudaGetSymbolAddress((void**)&pwpad,  g_wpad);
    cudaGetSymbolAddress((void**)&pqloc,  g_qloc);
    cudaGetSymbolAddress((void**)&pqrout, g_qrout);
    cudaGetSymbolAddress((void**)&pfq,    g_fq);
    cudaGetSymbolAddress((void**)&pattn,  g_attn);
    cudaGetSymbolAddress((void**)&pscore, g_score);
    cudaGetSymbolAddress((void**)&psn,    g_sn);

    const int R = BB * NN;
    const int TOT = BB * NN * EE;
    const int ATTN_SMEM = 2 * DKK * NP * (int)sizeof(float);  // 67,072 B
    static int smem_set = 0;
    if (!smem_set) {
        cudaFuncSetAttribute(attn3_kernel, cudaFuncAttributeMaxDynamicSharedMemorySize, ATTN_SMEM);
        smem_set = 1;
    }

    embed_kernel<<<(TOT + 255)/256, 256>>>(depot, cust, edW, edb, ecW, ecb);

    for (int i = 0; i < NLL; i++) {
        launch_gemm(px, Wq + (long)i*EE*EE, 0, 0, pq, R, EE, EE, 1, 0, 0, 0, 0);
        launch_gemm(px, Wk + (long)i*EE*EE, 0, 0, pk, R, EE, EE, 1, 0, 0, 0, 0);
        launch_gemm(px, Wv + (long)i*EE*EE, 0, 0, pv, R, EE, EE, 1, 0, 0, 0, 0);
        attn3_kernel<<<dim3(HH, BB), 256, ATTN_SMEM>>>(pq, pk, pv, (const float*)0, pmh);
        launch_gemm(pmh, Wc + (long)i*EE*EE, Wcb + (long)i*EE, px, py, R, EE, EE, 1, 0, 0, 0, 0);
        inorm_stats<<<dim3(BB, 8), EE>>>(py);
        inorm_fin<<<BB, EE>>>();
        inorm_apply<<<(TOT + 255)/256, 256>>>(py, n1g + (long)i*EE, n1b + (long)i*EE, px1);
        launch_gemm(px1, fW1 + (long)i*FFHH*EE, fb1 + (long)i*FFHH, 0, pffh, R, EE, FFHH, 1, 0, 0, 0, 1);
        launch_gemm(pffh, fW2 + (long)i*EE*FFHH, fb2 + (long)i*EE, px1, py, R, FFHH, EE, 1, 0, 0, 0, 0);
        inorm_stats<<<dim3(BB, 8), EE>>>(py);
        inorm_fin<<<BB, EE>>>();
        inorm_apply<<<(TOT + 255)/256, 256>>>(py, n2g + (long)i*EE, n2b + (long)i*EE, px);
    }

    launch_gemm(px, dWk, 0, 0, pkd, R, EE, EE, 1, 0, 0, 0, 0);
    launch_gemm(px, dWv, 0, 0, pvd, R, EE, EE, 1, 0, 0, 0, 0);
    encmean_kernel<<<BB, EE>>>();
    build_cat<<<BB*MM, EE>>>(loadv, cur, subn, subl, sel);
    padw_kernel<<<(EE*272 + 255)/256, 256>>>(dWqrt);
    launch_gemm(pcatloc,  dWqloc, 0, 0, pqloc,  R, 256, EE, 1, 0, 0, 0, 0);
    launch_gemm(pcatrout, pwpad,  0, 0, pqrout, R, 272, EE, 1, 0, 0, 0, 0);
    blend_kernel<<<(BB*MM*EE + 255)/256, 256>>>();
    attn3_kernel<<<dim3(HH, BB), 256, ATTN_SMEM>>>(pfq, pkd, pvd, mask, pattn);
    launch_gemm(pattn, dWc, dWcb, 0, pscore, R, EE, EE, 1, 0, 0, 0, 0);
    launch_gemm(pscore, px, 0, 0, psn, MM, EE, NN, BB,
                (long)MM*EE, (long)NN*EE, (long)MM*NN, 0);
    final_kernel<<<BB*MM, 256>>>(mask, out);
}

// round 4
// speedup vs baseline: 19.4210x; 1.1486x over previous
#include <cuda_runtime.h>
#include <cuda_bf16.h>
#include <math.h>
#include <stdint.h>

#define BB 32
#define NN 520
#define DEPOTN 20
#define CUSTN 500
#define EE 128
#define HH 8
#define DKK 16
#define FFHH 512
#define NLL 6
#define MM 520
#define LL 40
#define NP 524   // padded key stride in attention smem

// ---------------- scratch ----------------
__device__ __align__(16) float g_x   [BB*NN*EE];
__device__ __align__(16) float g_qkv [BB*NN*384];
__device__ __align__(16) float g_mh  [BB*NN*EE];
__device__ __align__(16) float g_y   [BB*NN*EE];
__device__ __align__(16) float g_x1  [BB*NN*EE];
__device__ __align__(16) float g_ffh [BB*NN*FFHH];
__device__ __align__(16) float g_part[BB*8*EE*2];
__device__ __align__(16) float g_stats[BB*EE*2];
__device__ __align__(16) float g_kvd [BB*NN*256];
__device__ __align__(16) float g_encmean[BB*EE];
__device__ __align__(16) float g_catloc [BB*MM*256];
__device__ __align__(16) float g_catrout[BB*MM*272];
__device__ __align__(16) float g_wpad[EE*272];
__device__ __align__(16) float g_wqkv[NLL*384*EE];
__device__ __align__(16) float g_wkv2[256*EE];
__device__ __align__(16) float g_qloc [BB*MM*EE];
__device__ __align__(16) float g_qrout[BB*MM*EE];
__device__ __align__(16) float g_fq   [BB*MM*EE];
__device__ __align__(16) float g_flag [BB*MM];
__device__ __align__(16) float g_attn [BB*MM*EE];
__device__ __align__(16) float g_score[BB*MM*EE];
__device__ __align__(16) float g_sn   [BB*MM*NN];

// ---------------- embedding ----------------
__global__ void embed_kernel(const float* __restrict__ dep, const float* __restrict__ cus,
                             const float* __restrict__ Wd, const float* __restrict__ bd,
                             const float* __restrict__ Wc, const float* __restrict__ bc)
{
    int idx = blockIdx.x * blockDim.x + threadIdx.x;
    if (idx >= BB*NN*EE) return;
    int e = idx % EE;
    int n = (idx / EE) % NN;
    int b = idx / (EE*NN);
    float acc;
    if (n < DEPOTN) {
        const float* f = dep + ((long)b*DEPOTN + n) * 4;
        acc = bd[e];
        #pragma unroll
        for (int j = 0; j < 4; j++) acc += f[j] * Wd[e*4 + j];
    } else {
        const float* f = cus + ((long)b*CUSTN + (n - DEPOTN)) * 3;
        acc = bc[e];
        #pragma unroll
        for (int j = 0; j < 3; j++) acc += f[j] * Wc[e*3 + j];
    }
    g_x[idx] = acc;
}

// ---------------- weight packing (QKV concat, decoder KV concat) ----------------
__global__ void pack_w(const float* __restrict__ Wq, const float* __restrict__ Wk,
                       const float* __restrict__ Wv, const float* __restrict__ dWk,
                       const float* __restrict__ dWv)
{
    int idx = blockIdx.x * blockDim.x + threadIdx.x;
    const int tot1 = NLL*384*EE;
    if (idx < tot1) {
        int col = idx % EE;
        int row = (idx / EE) % 384;
        int l   = idx / (EE*384);
        float v;
        if (row < 128)      v = Wq[((long)l*EE + row)*EE + col];
        else if (row < 256) v = Wk[((long)l*EE + row-128)*EE + col];
        else                v = Wv[((long)l*EE + row-256)*EE + col];
        g_wqkv[idx] = v;
    } else {
        int j = idx - tot1;
        if (j < 256*EE) {
            int col = j % EE;
            int row = j / EE;
            g_wkv2[j] = (row < 128) ? dWk[row*EE + col] : dWv[(row-128)*EE + col];
        }
    }
}

// ---------------- TC GEMM: bf16x3 split-precision, fp32 accuracy ----------------
// C = A @ W^T (+bias)(+resid)(+relu). A:(R,K) rm, W:(Cout,K) rm. K%16==0, Cout even.
#define SPITCH 24                 // bf16 elements per smem row (48 B, 16B aligned, conflict-free)
#define LO_OFF 6144               // bytes between hi and lo tiles (128*24*2)

__device__ __forceinline__ void cvt_store(const float* f, __nv_bfloat16* dsthi, __nv_bfloat16* dstlo)
{
    uint32_t hp[8], lp[8];
    #pragma unroll
    for (int j = 0; j < 8; j++) {
        float x0 = f[2*j], x1 = f[2*j+1];
        __nv_bfloat16 h0 = __float2bfloat16(x0);
        __nv_bfloat16 h1 = __float2bfloat16(x1);
        __nv_bfloat16 l0 = __float2bfloat16(x0 - __bfloat162float(h0));
        __nv_bfloat16 l1 = __float2bfloat16(x1 - __bfloat162float(h1));
        hp[j] = ((uint32_t)__bfloat16_as_ushort(h1) << 16) | __bfloat16_as_ushort(h0);
        lp[j] = ((uint32_t)__bfloat16_as_ushort(l1) << 16) | __bfloat16_as_ushort(l0);
    }
    *(uint4*)(dsthi)     = make_uint4(hp[0], hp[1], hp[2], hp[3]);
    *(uint4*)(dsthi + 8) = make_uint4(hp[4], hp[5], hp[6], hp[7]);
    *(uint4*)(dstlo)     = make_uint4(lp[0], lp[1], lp[2], lp[3]);
    *(uint4*)(dstlo + 8) = make_uint4(lp[4], lp[5], lp[6], lp[7]);
}

#define LDM4(r0,r1,r2,r3,addr) \
    asm volatile("ldmatrix.sync.aligned.m8n8.x4.shared.b16 {%0,%1,%2,%3},[%4];" \
                 : "=r"(r0),"=r"(r1),"=r"(r2),"=r"(r3) : "r"(addr))
#define LDM2(r0,r1,addr) \
    asm volatile("ldmatrix.sync.aligned.m8n8.x2.shared.b16 {%0,%1},[%2];" \
                 : "=r"(r0),"=r"(r1) : "r"(addr))
#define MMA16816(c,a,b) \
    asm volatile("mma.sync.aligned.m16n8k16.row.col.f32.bf16.bf16.f32 " \
                 "{%0,%1,%2,%3},{%4,%5,%6,%7},{%8,%9},{%0,%1,%2,%3};" \
                 : "+f"((c)[0]),"+f"((c)[1]),"+f"((c)[2]),"+f"((c)[3]) \
                 : "r"((a)[0]),"r"((a)[1]),"r"((a)[2]),"r"((a)[3]), "r"((b)[0]),"r"((b)[1]))

__global__ __launch_bounds__(256)
void gemm_tc(const float* __restrict__ A, const float* __restrict__ W,
             const float* __restrict__ bias, const float* __restrict__ resid,
             float* __restrict__ C, int R, int K, int Cout,
             long sA, long sW, long sC, int relu)
{
    int bz = blockIdx.z;
    A += (long)bz * sA; W += (long)bz * sW; C += (long)bz * sC;
    if (resid) resid += (long)bz * sC;

    __shared__ __align__(16) __nv_bfloat16 smem_t[4*128*SPITCH];
    __nv_bfloat16* sAhi = smem_t;
    __nv_bfloat16* sBhi = smem_t + 2*128*SPITCH;
    uint32_t sbase = (uint32_t)__cvta_generic_to_shared(smem_t);

    int tid = threadIdx.x, lane = tid & 31, warp = tid >> 5;
    int wm = warp >> 2, wn = warp & 3;
    int rowBase = blockIdx.x * 128, colBase = blockIdx.y * 128;

    // staging: threads 0-127 load A rows, 128-255 load W rows (16 floats/row per k-tile)
    int op = tid >> 7, r = tid & 127;
    int gr = (op ? colBase : rowBase) + r;
    bool valid = gr < (op ? Cout : R);
    const float* gptr = (op ? W : A) + (long)gr * K;
    __nv_bfloat16* dsthi = (op ? sBhi : sAhi) + r * SPITCH;
    __nv_bfloat16* dstlo = dsthi + 128*SPITCH;

    // ldmatrix addresses (fixed across k-loop; smem tile is only 16-k wide)
    uint32_t aAddr[4], bAddr[4];
    {
        int Lr = lane & 15, kh = (lane >> 4) * 8;
        #pragma unroll
        for (int i = 0; i < 4; i++) {
            int row = wm*64 + i*16 + Lr;
            aAddr[i] = sbase + (row*SPITCH + kh) * 2;
        }
        int Br = lane & 7, Bk = ((lane >> 3) & 1) * 8;
        #pragma unroll
        for (int j = 0; j < 4; j++) {
            int row = wn*32 + j*8 + Br;
            bAddr[j] = sbase + 2*128*SPITCH*2 + (row*SPITCH + Bk) * 2;
        }
    }

    float c[4][4][4];
    #pragma unroll
    for (int i = 0; i < 4; i++)
        #pragma unroll
        for (int j = 0; j < 4; j++)
            { c[i][j][0]=0.f; c[i][j][1]=0.f; c[i][j][2]=0.f; c[i][j][3]=0.f; }

    float stg[16];
    // preload k-tile 0
    if (valid) {
        #pragma unroll
        for (int q = 0; q < 4; q++) *(float4*)&stg[q*4] = *(const float4*)(gptr + q*4);
    } else {
        #pragma unroll
        for (int q = 0; q < 16; q++) stg[q] = 0.f;
    }

    int nk = K >> 4;
    for (int kt = 0; kt < nk; kt++) {
        __syncthreads();
        cvt_store(stg, dsthi, dstlo);
        if (kt + 1 < nk) {
            int k0 = (kt + 1) << 4;
            if (valid) {
                #pragma unroll
                for (int q = 0; q < 4; q++) *(float4*)&stg[q*4] = *(const float4*)(gptr + k0 + q*4);
            }
        }
        __syncthreads();

        uint32_t Ahi[4][4], Alo[4][4];
        #pragma unroll
        for (int i = 0; i < 4; i++) {
            LDM4(Ahi[i][0], Ahi[i][1], Ahi[i][2], Ahi[i][3], aAddr[i]);
            LDM4(Alo[i][0], Alo[i][1], Alo[i][2], Alo[i][3], aAddr[i] + LO_OFF);
        }
        #pragma unroll
        for (int j = 0; j < 4; j++) {
            uint32_t Bh[2], Bl[2];
            LDM2(Bh[0], Bh[1], bAddr[j]);
            LDM2(Bl[0], Bl[1], bAddr[j] + LO_OFF);
            #pragma unroll
            for (int i = 0; i < 4; i++) {
                MMA16816(c[i][j], Ahi[i], Bh);
                MMA16816(c[i][j], Ahi[i], Bl);
                MMA16816(c[i][j], Alo[i], Bh);
            }
        }
    }

    // epilogue
    int gid = lane >> 2, tig = lane & 3;
    #pragma unroll
    for (int i = 0; i < 4; i++) {
        int rbase = rowBase + wm*64 + i*16 + gid;
        #pragma unroll
        for (int j = 0; j < 4; j++) {
            int c0 = colBase + wn*32 + j*8 + tig*2;
            if (c0 >= Cout) continue;
            #pragma unroll
            for (int hh = 0; hh < 2; hh++) {
                int row = rbase + hh*8;
                if (row >= R) continue;
                float v0 = c[i][j][2*hh], v1 = c[i][j][2*hh+1];
                if (bias)  { v0 += bias[c0]; v1 += bias[c0+1]; }
                if (resid) {
                    float2 rv = *(const float2*)(resid + (long)row*Cout + c0);
                    v0 += rv.x; v1 += rv.y;
                }
                if (relu) { v0 = fmaxf(v0, 0.f); v1 = fmaxf(v1, 0.f); }
                *(float2*)(C + (long)row*Cout + c0) = make_float2(v0, v1);
            }
        }
    }
}

// ---------------- attention v3 (strided Q/K/V): 4 queries per warp pass ----------------
__global__ __launch_bounds__(256, 2)
void attn3_kernel(const float* __restrict__ Q, int ldq,
                  const float* __restrict__ Kt, int ldk,
                  const float* __restrict__ Vt, int ldv,
                  const float* __restrict__ mask, float* __restrict__ O)
{
    int h = blockIdx.x, b = blockIdx.y;
    extern __shared__ float sm[];
    float* Ks = sm;
    float* Vs = sm + DKK*NP;

    int tid = threadIdx.x;
    const float* Kb = Kt + (long)b*NN*ldk + h*DKK;
    const float* Vb = Vt + (long)b*NN*ldv + h*DKK;

    for (int idx = tid; idx < NN*4; idx += 256) {
        int n = idx >> 2;
        int c4 = (idx & 3) * 4;
        float4 kv = *(const float4*)(Kb + (long)n*ldk + c4);
        Ks[(c4+0)*NP+n]=kv.x; Ks[(c4+1)*NP+n]=kv.y; Ks[(c4+2)*NP+n]=kv.z; Ks[(c4+3)*NP+n]=kv.w;
        float4 vv = *(const float4*)(Vb + (long)n*ldv + c4);
        Vs[(c4+0)*NP+n]=vv.x; Vs[(c4+1)*NP+n]=vv.y; Vs[(c4+2)*NP+n]=vv.z; Vs[(c4+3)*NP+n]=vv.w;
    }
    __syncthreads();

    int warp = tid >> 5, lane = tid & 31;
    const unsigned FULL = 0xffffffffu;

    for (int p = warp; p < NN/4; p += 8) {
        int q0 = 4*p;
        const float* Qb = Q + ((long)b*NN + q0)*ldq + h*DKK;
        const float* mr = mask ? (mask + ((long)(b*MM + q0))*NN) : (const float*)0;

        float s0[17], s1[17], s2[17], s3[17];
        #pragma unroll
        for (int i = 0; i < 17; i++) { s0[i]=0.f; s1[i]=0.f; s2[i]=0.f; s3[i]=0.f; }

        #pragma unroll
        for (int th = 0; th < 2; th++) {
            float qr0[8], qr1[8], qr2[8], qr3[8];
            {
                float t0 = (lane < 8) ? Qb[0*ldq + th*8 + lane] : 0.f;
                float t1 = (lane < 8) ? Qb[1*ldq + th*8 + lane] : 0.f;
                float t2 = (lane < 8) ? Qb[2*ldq + th*8 + lane] : 0.f;
                float t3 = (lane < 8) ? Qb[3*ldq + th*8 + lane] : 0.f;
                #pragma unroll
                for (int t = 0; t < 8; t++) {
                    qr0[t] = __shfl_sync(FULL, t0, t);
                    qr1[t] = __shfl_sync(FULL, t1, t);
                    qr2[t] = __shfl_sync(FULL, t2, t);
                    qr3[t] = __shfl_sync(FULL, t3, t);
                }
            }
            #pragma unroll
            for (int i = 0; i < 17; i++) {
                int j = lane + 32*i;
                if (j < NN) {
                    float a0=0.f, a1=0.f, a2=0.f, a3=0.f;
                    #pragma unroll
                    for (int t = 0; t < 8; t++) {
                        float kv = Ks[(th*8 + t)*NP + j];
                        a0 += qr0[t]*kv; a1 += qr1[t]*kv;
                        a2 += qr2[t]*kv; a3 += qr3[t]*kv;
                    }
                    s0[i] += a0; s1[i] += a1; s2[i] += a2; s3[i] += a3;
                }
            }
        }

        float m0=-1e30f, m1=-1e30f, m2=-1e30f, m3=-1e30f;
        #pragma unroll
        for (int i = 0; i < 17; i++) {
            int j = lane + 32*i;
            if (j < NN) {
                float a0 = s0[i]*0.25f, a1 = s1[i]*0.25f, a2 = s2[i]*0.25f, a3 = s3[i]*0.25f;
                if (mr) {
                    a0 += mr[j]; a1 += mr[NN + j]; a2 += mr[2*NN + j]; a3 += mr[3*NN + j];
                }
                s0[i]=a0; s1[i]=a1; s2[i]=a2; s3[i]=a3;
                m0=fmaxf(m0,a0); m1=fmaxf(m1,a1); m2=fmaxf(m2,a2); m3=fmaxf(m3,a3);
            } else {
                s0[i]=-1e30f; s1[i]=-1e30f; s2[i]=-1e30f; s3[i]=-1e30f;
            }
        }
        #pragma unroll
        for (int off = 16; off > 0; off >>= 1) {
            m0 = fmaxf(m0, __shfl_xor_sync(FULL, m0, off));
            m1 = fmaxf(m1, __shfl_xor_sync(FULL, m1, off));
            m2 = fmaxf(m2, __shfl_xor_sync(FULL, m2, off));
            m3 = fmaxf(m3, __shfl_xor_sync(FULL, m3, off));
        }
        float u0=0.f, u1=0.f, u2=0.f, u3=0.f;
        #pragma unroll
        for (int i = 0; i < 17; i++) {
            float e0=__expf(s0[i]-m0), e1=__expf(s1[i]-m1);
            float e2=__expf(s2[i]-m2), e3=__expf(s3[i]-m3);
            s0[i]=e0; s1[i]=e1; s2[i]=e2; s3[i]=e3;
            u0+=e0; u1+=e1; u2+=e2; u3+=e3;
        }
        #pragma unroll
        for (int off = 16; off > 0; off >>= 1) {
            u0 += __shfl_xor_sync(FULL, u0, off);
            u1 += __shfl_xor_sync(FULL, u1, off);
            u2 += __shfl_xor_sync(FULL, u2, off);
            u3 += __shfl_xor_sync(FULL, u3, off);
        }
        float i0=1.f/u0, i1=1.f/u1, i2=1.f/u2, i3=1.f/u3;

        #pragma unroll
        for (int th = 0; th < 2; th++) {
            float o0[8], o1[8], o2[8], o3[8];
            #pragma unroll
            for (int t = 0; t < 8; t++) { o0[t]=0.f; o1[t]=0.f; o2[t]=0.f; o3[t]=0.f; }
            #pragma unroll
            for (int i = 0; i < 17; i++) {
                int j = lane + 32*i;
                if (j < NN) {
                    float w0=s0[i]*i0, w1=s1[i]*i1, w2=s2[i]*i2, w3=s3[i]*i3;
                    #pragma unroll
                    for (int t = 0; t < 8; t++) {
                        float vv = Vs[(th*8 + t)*NP + j];
                        o0[t]+=w0*vv; o1[t]+=w1*vv; o2[t]+=w2*vv; o3[t]+=w3*vv;
                    }
                }
            }
            #pragma unroll
            for (int t = 0; t < 8; t++) {
                #pragma unroll
                for (int off = 16; off > 0; off >>= 1) {
                    o0[t] += __shfl_xor_sync(FULL, o0[t], off);
                    o1[t] += __shfl_xor_sync(FULL, o1[t], off);
                    o2[t] += __shfl_xor_sync(FULL, o2[t], off);
                    o3[t] += __shfl_xor_sync(FULL, o3[t], off);
                }
            }
            if (lane == 0) {
                float* d = O + ((long)(b*NN + q0))*EE + h*DKK + th*8;
                ((float4*)d)[0]          = make_float4(o0[0],o0[1],o0[2],o0[3]);
                ((float4*)d)[1]          = make_float4(o0[4],o0[5],o0[6],o0[7]);
                ((float4*)(d+EE))[0]     = make_float4(o1[0],o1[1],o1[2],o1[3]);
                ((float4*)(d+EE))[1]     = make_float4(o1[4],o1[5],o1[6],o1[7]);
                ((float4*)(d+2*EE))[0]   = make_float4(o2[0],o2[1],o2[2],o2[3]);
                ((float4*)(d+2*EE))[1]   = make_float4(o2[4],o2[5],o2[6],o2[7]);
                ((float4*)(d+3*EE))[0]   = make_float4(o3[0],o3[1],o3[2],o3[3]);
                ((float4*)(d+3*EE))[1]   = make_float4(o3[4],o3[5],o3[6],o3[7]);
            }
        }
    }
}

// ---------------- instance norm ----------------
__global__ void inorm_stats(const float* __restrict__ Y)
{
    int b = blockIdx.x, ch = blockIdx.y, e = threadIdx.x;
    float s1 = 0.f, s2 = 0.f;
    for (int n = ch; n < NN; n += 8) {
        float v = Y[((long)(b*NN + n))*EE + e];
        s1 += v; s2 += v*v;
    }
    int idx = (b*8 + ch)*EE + e;
    g_part[idx*2]   = s1;
    g_part[idx*2+1] = s2;
}
__global__ void inorm_fin()
{
    int b = blockIdx.x, e = threadIdx.x;
    float s1 = 0.f, s2 = 0.f;
    for (int c = 0; c < 8; c++) {
        int idx = (b*8 + c)*EE + e;
        s1 += g_part[idx*2]; s2 += g_part[idx*2+1];
    }
    float mean = s1 / (float)NN;
    float var  = s2 / (float)NN - mean*mean;
    g_stats[(b*EE+e)*2]   = mean;
    g_stats[(b*EE+e)*2+1] = rsqrtf(var + 1e-5f);
}
__global__ void inorm_apply(const float* __restrict__ Y, const float* __restrict__ gg,
                            const float* __restrict__ bt, float* __restrict__ Xo)
{
    int idx = blockIdx.x * blockDim.x + threadIdx.x;
    if (idx >= BB*NN*EE) return;
    int e = idx % EE;
    int b = idx / (NN*EE);
    float mean = g_stats[(b*EE+e)*2];
    float istd = g_stats[(b*EE+e)*2+1];
    Xo[idx] = (Y[idx] - mean) * istd * gg[e] + bt[e];
}

// ---------------- decoder helpers ----------------
__global__ void encmean_kernel()
{
    int b = blockIdx.x, e = threadIdx.x;
    float s = 0.f;
    for (int n = 0; n < NN; n++) s += g_x[((long)(b*NN + n))*EE + e];
    g_encmean[b*EE + e] = s / (float)NN;
}

__global__ void build_cat(const float* __restrict__ loadv, const int* __restrict__ cur,
                          const int* __restrict__ subn, const int* __restrict__ subl,
                          const int* __restrict__ sel)
{
    int r = blockIdx.x;
    int b = r / MM;
    int e = threadIdx.x;
    int c = cur[r];
    float le = g_x[((long)(b*NN + c))*EE + e];

    int len = subl[r];
    const int* nodes = subn + (long)r*LL;
    float ssum = 0.f; int cnt = 0;
    for (int l = 0; l < LL; l++) {
        int nd = nodes[l];
        if (l < len && nd >= DEPOTN) {
            ssum += g_x[((long)(b*NN + nd))*EE + e];
            cnt++;
        }
    }
    float cntf = (cnt > 0) ? (float)cnt : 1.f;
    float smean = ssum / cntf;

    g_catloc[(long)r*256 + e]        = le;
    g_catloc[(long)r*256 + 128 + e]  = smean;
    g_catrout[(long)r*272 + e]       = le;
    g_catrout[(long)r*272 + 128 + e] = g_encmean[b*EE + e];
    if (e == 0) g_catrout[(long)r*272 + 256] = loadv[r];
    if (e >= 1 && e < 16) g_catrout[(long)r*272 + 256 + e] = 0.f;
    if (e == 0) {
        int s2 = sel[(long)r*4 + 2];
        g_flag[r] = (s2 >= DEPOTN && c < DEPOTN) ? 1.f : 0.f;
    }
}

__global__ void padw_kernel(const float* __restrict__ Wr)
{
    int idx = blockIdx.x * blockDim.x + threadIdx.x;
    if (idx >= EE*272) return;
    int rr = idx / 272, cc = idx % 272;
    g_wpad[idx] = (cc < 257) ? Wr[rr*257 + cc] : 0.f;
}

__global__ void blend_kernel()
{
    int idx = blockIdx.x * blockDim.x + threadIdx.x;
    if (idx >= BB*MM*EE) return;
    int r = idx / EE;
    float f = g_flag[r];
    g_fq[idx] = f * g_qloc[idx] + (1.f - f) * g_qrout[idx];
}

// ---------------- final tanh-clip + mask + softmax ----------------
__global__ void final_kernel(const float* __restrict__ mask, float* __restrict__ out)
{
    int r = blockIdx.x;
    int tid = threadIdx.x;
    __shared__ float buf[NN];
    __shared__ float red[256];
    const float* sn = g_sn + (long)r*NN;
    const float* mk = mask + (long)r*NN;
    const float invs = 0.08838834764831845f;

    float lm = -1e30f;
    for (int j = tid; j < NN; j += 256) {
        float v = 10.f * tanhf(sn[j] * invs) + mk[j];
        buf[j] = v;
        lm = fmaxf(lm, v);
    }
    red[tid] = lm; __syncthreads();
    for (int off = 128; off > 0; off >>= 1) {
        if (tid < off) red[tid] = fmaxf(red[tid], red[tid+off]);
        __syncthreads();
    }
    float mx = red[0]; __syncthreads();

    float ls = 0.f;
    for (int j = tid; j < NN; j += 256) {
        float e0 = __expf(buf[j] - mx);
        buf[j] = e0; ls += e0;
    }
    red[tid] = ls; __syncthreads();
    for (int off = 128; off > 0; off >>= 1) {
        if (tid < off) red[tid] += red[tid+off];
        __syncthreads();
    }
    float inv = 1.f / red[0];
    for (int j = tid; j < NN; j += 256)
        out[(long)r*NN + j] = buf[j] * inv;
}

// ---------------- host ----------------
static void launch_gemm(const float* A, const float* W, const float* bias,
                        const float* resid, float* C, int R, int K, int Cout,
                        int batch, long sA, long sW, long sC, int relu)
{
    dim3 grid((R + 127) / 128, (Cout + 127) / 128, batch);
    gemm_tc<<<grid, 256>>>(A, W, bias, resid, C, R, K, Cout, sA, sW, sC, relu);
}

extern "C" void kernel_launch(void* const* d_in, const int* in_sizes, int n_in,
                              void* d_out, int out_size)
{
    const float* depot  = (const float*)d_in[0];
    const float* cust   = (const float*)d_in[1];
    const float* mask   = (const float*)d_in[2];
    const float* loadv  = (const float*)d_in[3];
    const int*   cur    = (const int*)d_in[4];
    const int*   subn   = (const int*)d_in[5];
    const int*   subl   = (const int*)d_in[6];
    const int*   sel    = (const int*)d_in[7];
    const float* edW    = (const float*)d_in[8];
    const float* edb    = (const float*)d_in[9];
    const float* ecW    = (const float*)d_in[10];
    const float* ecb    = (const float*)d_in[11];
    const float* Wq     = (const float*)d_in[12];
    const float* Wk     = (const float*)d_in[13];
    const float* Wv     = (const float*)d_in[14];
    const float* Wc     = (const float*)d_in[15];
    const float* Wcb    = (const float*)d_in[16];
    const float* n1g    = (const float*)d_in[17];
    const float* n1b    = (const float*)d_in[18];
    const float* fW1    = (const float*)d_in[19];
    const float* fb1    = (const float*)d_in[20];
    const float* fW2    = (const float*)d_in[21];
    const float* fb2    = (const float*)d_in[22];
    const float* n2g    = (const float*)d_in[23];
    const float* n2b    = (const float*)d_in[24];
    const float* dWqloc = (const float*)d_in[25];
    const float* dWqrt  = (const float*)d_in[26];
    const float* dWk    = (const float*)d_in[27];
    const float* dWv    = (const float*)d_in[28];
    const float* dWc    = (const float*)d_in[29];
    const float* dWcb   = (const float*)d_in[30];
    float* out = (float*)d_out;

    float *px, *pqkv, *pmh, *py, *px1, *pffh;
    float *pkvd, *pcatloc, *pcatrout, *pwpad, *pwqkv, *pwkv2;
    float *pqloc, *pqrout, *pfq, *pattn, *pscore, *psn;
    cudaGetSymbolAddress((void**)&px,   g_x);
    cudaGetSymbolAddress((void**)&pqkv, g_qkv);
    cudaGetSymbolAddress((void**)&pmh,  g_mh);
    cudaGetSymbolAddress((void**)&py,   g_y);
    cudaGetSymbolAddress((void**)&px1,  g_x1);
    cudaGetSymbolAddress((void**)&pffh, g_ffh);
    cudaGetSymbolAddress((void**)&pkvd, g_kvd);
    cudaGetSymbolAddress((void**)&pcatloc,  g_catloc);
    cudaGetSymbolAddress((void**)&pcatrout, g_catrout);
    cudaGetSymbolAddress((void**)&pwpad,  g_wpad);
    cudaGetSymbolAddress((void**)&pwqkv,  g_wqkv);
    cudaGetSymbolAddress((void**)&pwkv2,  g_wkv2);
    cudaGetSymbolAddress((void**)&pqloc,  g_qloc);
    cudaGetSymbolAddress((void**)&pqrout, g_qrout);
    cudaGetSymbolAddress((void**)&pfq,    g_fq);
    cudaGetSymbolAddress((void**)&pattn,  g_attn);
    cudaGetSymbolAddress((void**)&pscore, g_score);
    cudaGetSymbolAddress((void**)&psn,    g_sn);

    const int R = BB * NN;
    const int TOT = BB * NN * EE;
    const int ATTN_SMEM = 2 * DKK * NP * (int)sizeof(float);  // 67,072 B
    static int smem_set = 0;
    if (!smem_set) {
        cudaFuncSetAttribute(attn3_kernel, cudaFuncAttributeMaxDynamicSharedMemorySize, ATTN_SMEM);
        smem_set = 1;
    }

    embed_kernel<<<(TOT + 255)/256, 256>>>(depot, cust, edW, edb, ecW, ecb);
    pack_w<<<(NLL*384*EE + 256*EE + 255)/256, 256>>>(Wq, Wk, Wv, dWk, dWv);
    padw_kernel<<<(EE*272 + 255)/256, 256>>>(dWqrt);

    for (int i = 0; i < NLL; i++) {
        // fused QKV projection: Cout = 384
        launch_gemm(px, pwqkv + (long)i*384*EE, 0, 0, pqkv, R, EE, 384, 1, 0, 0, 0, 0);
        attn3_kernel<<<dim3(HH, BB), 256, ATTN_SMEM>>>(pqkv, 384, pqkv + 128, 384,
                                                       pqkv + 256, 384, (const float*)0, pmh);
        launch_gemm(pmh, Wc + (long)i*EE*EE, Wcb + (long)i*EE, px, py, R, EE, EE, 1, 0, 0, 0, 0);
        inorm_stats<<<dim3(BB, 8), EE>>>(py);
        inorm_fin<<<BB, EE>>>();
        inorm_apply<<<(TOT + 255)/256, 256>>>(py, n1g + (long)i*EE, n1b + (long)i*EE, px1);
        launch_gemm(px1, fW1 + (long)i*FFHH*EE, fb1 + (long)i*FFHH, 0, pffh, R, EE, FFHH, 1, 0, 0, 0, 1);
        launch_gemm(pffh, fW2 + (long)i*EE*FFHH, fb2 + (long)i*EE, px1, py, R, FFHH, EE, 1, 0, 0, 0, 0);
        inorm_stats<<<dim3(BB, 8), EE>>>(py);
        inorm_fin<<<BB, EE>>>();
        inorm_apply<<<(TOT + 255)/256, 256>>>(py, n2g + (long)i*EE, n2b + (long)i*EE, px);
    }

    // ---- decoder ----
    launch_gemm(px, pwkv2, 0, 0, pkvd, R, EE, 256, 1, 0, 0, 0, 0);  // fused dec K/V
    encmean_kernel<<<BB, EE>>>();
    build_cat<<<BB*MM, EE>>>(loadv, cur, subn, subl, sel);
    launch_gemm(pcatloc,  dWqloc, 0, 0, pqloc,  R, 256, EE, 1, 0, 0, 0, 0);
    launch_gemm(pcatrout, pwpad,  0, 0, pqrout, R, 272, EE, 1, 0, 0, 0, 0);
    blend_kernel<<<(BB*MM*EE + 255)/256, 256>>>();
    attn3_kernel<<<dim3(HH, BB), 256, ATTN_SMEM>>>(pfq, 128, pkvd, 256, pkvd + 128, 256, mask, pattn);
    launch_gemm(pattn, dWc, dWcb, 0, pscore, R, EE, EE, 1, 0, 0, 0, 0);
    launch_gemm(pscore, px, 0, 0, psn, MM, EE, NN, BB,
                (long)MM*EE, (long)NN*EE, (long)MM*NN, 0);
    final_kernel<<<BB*MM, 256>>>(mask, out);
}

// round 5
// speedup vs baseline: 20.6599x; 1.0638x over previous
#include <cuda_runtime.h>
#include <cuda_bf16.h>
#include <math.h>
#include <stdint.h>

#define BB 32
#define NN 520
#define DEPOTN 20
#define CUSTN 500
#define EE 128
#define HH 8
#define DKK 16
#define FFHH 512
#define NLL 6
#define MM 520
#define LL 40
#define NP 524
#define KRT 288          // padded routing K (257 -> 288, mult of 32)

typedef __nv_bfloat16 bf16;

// ---------------- fp32 scratch ----------------
__device__ __align__(16) float g_x   [BB*NN*EE];
__device__ __align__(16) float g_qkv [BB*NN*384];
__device__ __align__(16) float g_y   [BB*NN*EE];
__device__ __align__(16) float g_x1  [BB*NN*EE];
__device__ __align__(16) float g_part[BB*8*EE*2];
__device__ __align__(16) float g_stats[BB*EE*2];
__device__ __align__(16) float g_kvd [BB*NN*256];
__device__ __align__(16) float g_encmean[BB*EE];
__device__ __align__(16) float g_qloc [BB*MM*EE];
__device__ __align__(16) float g_qrout[BB*MM*EE];
__device__ __align__(16) float g_fq   [BB*MM*EE];
__device__ __align__(16) float g_flag [BB*MM];
__device__ __align__(16) float g_sn   [BB*MM*NN];

// ---------------- bf16 hi/lo scratch ----------------
__device__ __align__(16) bf16 g_xh[BB*NN*EE],      g_xl[BB*NN*EE];
__device__ __align__(16) bf16 g_x1h[BB*NN*EE],     g_x1l[BB*NN*EE];
__device__ __align__(16) bf16 g_mhh[BB*NN*EE],     g_mhl[BB*NN*EE];
__device__ __align__(16) bf16 g_ffhh[BB*NN*FFHH],  g_ffhl[BB*NN*FFHH];
__device__ __align__(16) bf16 g_attnh[BB*MM*EE],   g_attnl[BB*MM*EE];
__device__ __align__(16) bf16 g_scoreh[BB*MM*EE],  g_scorel[BB*MM*EE];
__device__ __align__(16) bf16 g_catlh[BB*MM*256],  g_catll[BB*MM*256];
__device__ __align__(16) bf16 g_catrh[BB*MM*KRT],  g_catrl[BB*MM*KRT];
// weights
__device__ __align__(16) bf16 g_wqkvh[NLL*384*EE], g_wqkvl[NLL*384*EE];
__device__ __align__(16) bf16 g_wch[NLL*EE*EE],    g_wcl[NLL*EE*EE];
__device__ __align__(16) bf16 g_f1h[NLL*FFHH*EE],  g_f1l[NLL*FFHH*EE];
__device__ __align__(16) bf16 g_f2h[NLL*EE*FFHH],  g_f2l[NLL*EE*FFHH];
__device__ __align__(16) bf16 g_wkvh[256*EE],      g_wkvl[256*EE];
__device__ __align__(16) bf16 g_wqlh[EE*256],      g_wqll[EE*256];
__device__ __align__(16) bf16 g_wpah[EE*KRT],      g_wpal[EE*KRT];
__device__ __align__(16) bf16 g_wdch[EE*EE],       g_wdcl[EE*EE];

__device__ __forceinline__ void split1(float x, bf16* h, bf16* l)
{
    bf16 hv = __float2bfloat16(x);
    *h = hv;
    *l = __float2bfloat16(x - __bfloat162float(hv));
}

// ---------------- generic fp32 -> hi/lo ----------------
__global__ void cvt_split(const float* __restrict__ s, bf16* __restrict__ h,
                          bf16* __restrict__ l, int n)
{
    int i = blockIdx.x * blockDim.x + threadIdx.x;
    if (i < n) split1(s[i], h + i, l + i);
}

// ---------------- embedding (emits fp32 + hi/lo) ----------------
__global__ void embed_kernel(const float* __restrict__ dep, const float* __restrict__ cus,
                             const float* __restrict__ Wd, const float* __restrict__ bd,
                             const float* __restrict__ Wc, const float* __restrict__ bc)
{
    int idx = blockIdx.x * blockDim.x + threadIdx.x;
    if (idx >= BB*NN*EE) return;
    int e = idx % EE;
    int n = (idx / EE) % NN;
    int b = idx / (EE*NN);
    float acc;
    if (n < DEPOTN) {
        const float* f = dep + ((long)b*DEPOTN + n) * 4;
        acc = bd[e];
        #pragma unroll
        for (int j = 0; j < 4; j++) acc += f[j] * Wd[e*4 + j];
    } else {
        const float* f = cus + ((long)b*CUSTN + (n - DEPOTN)) * 3;
        acc = bc[e];
        #pragma unroll
        for (int j = 0; j < 3; j++) acc += f[j] * Wc[e*3 + j];
    }
    g_x[idx] = acc;
    split1(acc, g_xh + idx, g_xl + idx);
}

// ---------------- weight packing (QKV, dec KV) with split ----------------
__global__ void pack_w(const float* __restrict__ Wq, const float* __restrict__ Wk,
                       const float* __restrict__ Wv, const float* __restrict__ dWk,
                       const float* __restrict__ dWv)
{
    int idx = blockIdx.x * blockDim.x + threadIdx.x;
    const int tot1 = NLL*384*EE;
    if (idx < tot1) {
        int col = idx % EE;
        int row = (idx / EE) % 384;
        int l   = idx / (EE*384);
        float v;
        if (row < 128)      v = Wq[((long)l*EE + row)*EE + col];
        else if (row < 256) v = Wk[((long)l*EE + row-128)*EE + col];
        else                v = Wv[((long)l*EE + row-256)*EE + col];
        split1(v, g_wqkvh + idx, g_wqkvl + idx);
    } else {
        int j = idx - tot1;
        if (j < 256*EE) {
            int col = j % EE;
            int row = j / EE;
            float v = (row < 128) ? dWk[row*EE + col] : dWv[(row-128)*EE + col];
            split1(v, g_wkvh + j, g_wkvl + j);
        }
    }
}

__global__ void padw_kernel(const float* __restrict__ Wr)
{
    int idx = blockIdx.x * blockDim.x + threadIdx.x;
    if (idx >= EE*KRT) return;
    int rr = idx / KRT, cc = idx % KRT;
    float v = (cc < 257) ? Wr[rr*257 + cc] : 0.f;
    split1(v, g_wpah + idx, g_wpal + idx);
}

// ---------------- TC GEMM v2: pure bf16 hi/lo, cp.async double buffer ----------------
// C = A @ B^T. A:(R,K) bf16 hi/lo, B:(Cout,K) bf16 hi/lo. K % 32 == 0.
// Output: fp32 C (+bias,+resid,+relu) and/or bf16 hi/lo Chi/Clo.
#define SP 40                    // bf16 per smem row (32 + 8 pad); 80 B stride
#define MAT 10240                // bytes per matrix tile (128*80)
#define STAGE 40960              // bytes per stage (4 matrices)

#define LDM4(r0,r1,r2,r3,addr) \
    asm volatile("ldmatrix.sync.aligned.m8n8.x4.shared.b16 {%0,%1,%2,%3},[%4];" \
                 : "=r"(r0),"=r"(r1),"=r"(r2),"=r"(r3) : "r"(addr))
#define LDM2(r0,r1,addr) \
    asm volatile("ldmatrix.sync.aligned.m8n8.x2.shared.b16 {%0,%1},[%2];" \
                 : "=r"(r0),"=r"(r1) : "r"(addr))
#define MMA16816(c,a,b) \
    asm volatile("mma.sync.aligned.m16n8k16.row.col.f32.bf16.bf16.f32 " \
                 "{%0,%1,%2,%3},{%4,%5,%6,%7},{%8,%9},{%0,%1,%2,%3};" \
                 : "+f"((c)[0]),"+f"((c)[1]),"+f"((c)[2]),"+f"((c)[3]) \
                 : "r"((a)[0]),"r"((a)[1]),"r"((a)[2]),"r"((a)[3]), "r"((b)[0]),"r"((b)[1]))

__global__ __launch_bounds__(256, 2)
void gemm_tc2(const bf16* __restrict__ Ahi, const bf16* __restrict__ Alo,
              const bf16* __restrict__ Bhi, const bf16* __restrict__ Blo,
              const float* __restrict__ bias, const float* __restrict__ resid,
              float* __restrict__ C, bf16* __restrict__ Chi, bf16* __restrict__ Clo,
              int R, int K, int Cout, long sA, long sB, long sC, int relu)
{
    int bz = blockIdx.z;
    Ahi += (long)bz*sA; Alo += (long)bz*sA;
    Bhi += (long)bz*sB; Blo += (long)bz*sB;
    if (C)     C   += (long)bz*sC;
    if (Chi) { Chi += (long)bz*sC; Clo += (long)bz*sC; }
    if (resid) resid += (long)bz*sC;

    extern __shared__ bf16 smb[];
    uint32_t sb = (uint32_t)__cvta_generic_to_shared(smb);

    int tid = threadIdx.x, lane = tid & 31, warp = tid >> 5;
    int wm = warp >> 2, wn = warp & 3;
    int rowBase = blockIdx.x * 128, colBase = blockIdx.y * 128;

    float c[4][4][4];
    #pragma unroll
    for (int i = 0; i < 4; i++)
        #pragma unroll
        for (int j = 0; j < 4; j++)
            { c[i][j][0]=0.f; c[i][j][1]=0.f; c[i][j][2]=0.f; c[i][j][3]=0.f; }

    const bf16* bases[4] = { Ahi, Alo, Bhi, Blo };

    int nk = K >> 5;

    // staging: 2048 cp.async 16B ops per stage, 8 per thread
    #define FILL(st, kt) do { \
        int k0 = (kt) << 5; \
        _Pragma("unroll") \
        for (int t = 0; t < 8; t++) { \
            int o = tid + t*256; \
            int m = o >> 9, r = (o >> 2) & 127, seg = o & 3; \
            int gr = ((m < 2) ? rowBase : colBase) + r; \
            int lim = (m < 2) ? R : Cout; \
            long grc = (gr < lim) ? gr : 0; \
            const bf16* src = bases[m] + grc*K + k0 + seg*8; \
            uint32_t dst = sb + (st)*STAGE + m*MAT + r*80 + seg*16; \
            int nbytes = (gr < lim) ? 16 : 0; \
            asm volatile("cp.async.ca.shared.global [%0],[%1],16,%2;" \
                         :: "r"(dst), "l"(src), "r"(nbytes)); \
        } \
        asm volatile("cp.async.commit_group;"); \
    } while (0)

    FILL(0, 0);

    int ar = lane & 15, ak = (lane >> 4);
    int br = lane & 7,  bk = (lane >> 3) & 1;

    for (int kt = 0; kt < nk; kt++) {
        int st = kt & 1;
        if (kt + 1 < nk) {
            FILL(st ^ 1, kt + 1);
            asm volatile("cp.async.wait_group 1;");
        } else {
            asm volatile("cp.async.wait_group 0;");
        }
        __syncthreads();

        uint32_t aOff = sb + st*STAGE;
        uint32_t bOff = aOff + 2*MAT;
        #pragma unroll
        for (int ks = 0; ks < 2; ks++) {
            uint32_t Ah[4][4], Al[4][4];
            #pragma unroll
            for (int i = 0; i < 4; i++) {
                uint32_t ad = aOff + (uint32_t)((wm*64 + i*16 + ar)*80 + ak*16 + ks*32);
                LDM4(Ah[i][0], Ah[i][1], Ah[i][2], Ah[i][3], ad);
                LDM4(Al[i][0], Al[i][1], Al[i][2], Al[i][3], ad + MAT);
            }
            #pragma unroll
            for (int j = 0; j < 4; j++) {
                uint32_t bd = bOff + (uint32_t)((wn*32 + j*8 + br)*80 + bk*16 + ks*32);
                uint32_t Bh[2], Bl[2];
                LDM2(Bh[0], Bh[1], bd);
                LDM2(Bl[0], Bl[1], bd + MAT);
                #pragma unroll
                for (int i = 0; i < 4; i++) {
                    MMA16816(c[i][j], Ah[i], Bh);
                    MMA16816(c[i][j], Ah[i], Bl);
                    MMA16816(c[i][j], Al[i], Bh);
                }
            }
        }
        __syncthreads();
    }

    int gid = lane >> 2, tig = lane & 3;
    #pragma unroll
    for (int i = 0; i < 4; i++) {
        int rbase = rowBase + wm*64 + i*16 + gid;
        #pragma unroll
        for (int j = 0; j < 4; j++) {
            int c0 = colBase + wn*32 + j*8 + tig*2;
            if (c0 >= Cout) continue;
            #pragma unroll
            for (int hh = 0; hh < 2; hh++) {
                int row = rbase + hh*8;
                if (row >= R) continue;
                float v0 = c[i][j][2*hh], v1 = c[i][j][2*hh+1];
                if (bias)  { v0 += bias[c0]; v1 += bias[c0+1]; }
                if (resid) {
                    float2 rv = *(const float2*)(resid + (long)row*Cout + c0);
                    v0 += rv.x; v1 += rv.y;
                }
                if (relu) { v0 = fmaxf(v0, 0.f); v1 = fmaxf(v1, 0.f); }
                if (C) *(float2*)(C + (long)row*Cout + c0) = make_float2(v0, v1);
                if (Chi) {
                    bf16 h0 = __float2bfloat16(v0);
                    bf16 h1 = __float2bfloat16(v1);
                    bf16 l0 = __float2bfloat16(v0 - __bfloat162float(h0));
                    bf16 l1 = __float2bfloat16(v1 - __bfloat162float(h1));
                    uint32_t hp = ((uint32_t)__bfloat16_as_ushort(h1) << 16) | __bfloat16_as_ushort(h0);
                    uint32_t lp = ((uint32_t)__bfloat16_as_ushort(l1) << 16) | __bfloat16_as_ushort(l0);
                    *(uint32_t*)(Chi + (long)row*Cout + c0) = hp;
                    *(uint32_t*)(Clo + (long)row*Cout + c0) = lp;
                }
            }
        }
    }
}

// ---------------- attention: strided fp32 in, bf16 hi/lo out ----------------
__device__ __forceinline__ void wsplit8(const float* o, bf16* dh, bf16* dl)
{
    uint32_t hp[4], lp[4];
    #pragma unroll
    for (int j = 0; j < 4; j++) {
        bf16 h0 = __float2bfloat16(o[2*j]);
        bf16 h1 = __float2bfloat16(o[2*j+1]);
        bf16 l0 = __float2bfloat16(o[2*j]   - __bfloat162float(h0));
        bf16 l1 = __float2bfloat16(o[2*j+1] - __bfloat162float(h1));
        hp[j] = ((uint32_t)__bfloat16_as_ushort(h1) << 16) | __bfloat16_as_ushort(h0);
        lp[j] = ((uint32_t)__bfloat16_as_ushort(l1) << 16) | __bfloat16_as_ushort(l0);
    }
    *(uint4*)dh = make_uint4(hp[0], hp[1], hp[2], hp[3]);
    *(uint4*)dl = make_uint4(lp[0], lp[1], lp[2], lp[3]);
}

__global__ __launch_bounds__(256, 2)
void attn3_kernel(const float* __restrict__ Q, int ldq,
                  const float* __restrict__ Kt, int ldk,
                  const float* __restrict__ Vt, int ldv,
                  const float* __restrict__ mask,
                  bf16* __restrict__ Oh, bf16* __restrict__ Ol)
{
    int h = blockIdx.x, b = blockIdx.y;
    extern __shared__ float sm[];
    float* Ks = sm;
    float* Vs = sm + DKK*NP;

    int tid = threadIdx.x;
    const float* Kb = Kt + (long)b*NN*ldk + h*DKK;
    const float* Vb = Vt + (long)b*NN*ldv + h*DKK;

    for (int idx = tid; idx < NN*4; idx += 256) {
        int n = idx >> 2;
        int c4 = (idx & 3) * 4;
        float4 kv = *(const float4*)(Kb + (long)n*ldk + c4);
        Ks[(c4+0)*NP+n]=kv.x; Ks[(c4+1)*NP+n]=kv.y; Ks[(c4+2)*NP+n]=kv.z; Ks[(c4+3)*NP+n]=kv.w;
        float4 vv = *(const float4*)(Vb + (long)n*ldv + c4);
        Vs[(c4+0)*NP+n]=vv.x; Vs[(c4+1)*NP+n]=vv.y; Vs[(c4+2)*NP+n]=vv.z; Vs[(c4+3)*NP+n]=vv.w;
    }
    __syncthreads();

    int warp = tid >> 5, lane = tid & 31;
    const unsigned FULL = 0xffffffffu;

    for (int p = warp; p < NN/4; p += 8) {
        int q0 = 4*p;
        const float* Qb = Q + ((long)b*NN + q0)*ldq + h*DKK;
        const float* mr = mask ? (mask + ((long)(b*MM + q0))*NN) : (const float*)0;

        float s0[17], s1[17], s2[17], s3[17];
        #pragma unroll
        for (int i = 0; i < 17; i++) { s0[i]=0.f; s1[i]=0.f; s2[i]=0.f; s3[i]=0.f; }

        #pragma unroll
        for (int th = 0; th < 2; th++) {
            float qr0[8], qr1[8], qr2[8], qr3[8];
            {
                float t0 = (lane < 8) ? Qb[0*ldq + th*8 + lane] : 0.f;
                float t1 = (lane < 8) ? Qb[1*ldq + th*8 + lane] : 0.f;
                float t2 = (lane < 8) ? Qb[2*ldq + th*8 + lane] : 0.f;
                float t3 = (lane < 8) ? Qb[3*ldq + th*8 + lane] : 0.f;
                #pragma unroll
                for (int t = 0; t < 8; t++) {
                    qr0[t] = __shfl_sync(FULL, t0, t);
                    qr1[t] = __shfl_sync(FULL, t1, t);
                    qr2[t] = __shfl_sync(FULL, t2, t);
                    qr3[t] = __shfl_sync(FULL, t3, t);
                }
            }
            #pragma unroll
            for (int i = 0; i < 17; i++) {
                int j = lane + 32*i;
                if (j < NN) {
                    float a0=0.f, a1=0.f, a2=0.f, a3=0.f;
                    #pragma unroll
                    for (int t = 0; t < 8; t++) {
                        float kv = Ks[(th*8 + t)*NP + j];
                        a0 += qr0[t]*kv; a1 += qr1[t]*kv;
                        a2 += qr2[t]*kv; a3 += qr3[t]*kv;
                    }
                    s0[i] += a0; s1[i] += a1; s2[i] += a2; s3[i] += a3;
                }
            }
        }

        float m0=-1e30f, m1=-1e30f, m2=-1e30f, m3=-1e30f;
        #pragma unroll
        for (int i = 0; i < 17; i++) {
            int j = lane + 32*i;
            if (j < NN) {
                float a0 = s0[i]*0.25f, a1 = s1[i]*0.25f, a2 = s2[i]*0.25f, a3 = s3[i]*0.25f;
                if (mr) {
                    a0 += mr[j]; a1 += mr[NN + j]; a2 += mr[2*NN + j]; a3 += mr[3*NN + j];
                }
                s0[i]=a0; s1[i]=a1; s2[i]=a2; s3[i]=a3;
                m0=fmaxf(m0,a0); m1=fmaxf(m1,a1); m2=fmaxf(m2,a2); m3=fmaxf(m3,a3);
            } else {
                s0[i]=-1e30f; s1[i]=-1e30f; s2[i]=-1e30f; s3[i]=-1e30f;
            }
        }
        #pragma unroll
        for (int off = 16; off > 0; off >>= 1) {
            m0 = fmaxf(m0, __shfl_xor_sync(FULL, m0, off));
            m1 = fmaxf(m1, __shfl_xor_sync(FULL, m1, off));
            m2 = fmaxf(m2, __shfl_xor_sync(FULL, m2, off));
            m3 = fmaxf(m3, __shfl_xor_sync(FULL, m3, off));
        }
        float u0=0.f, u1=0.f, u2=0.f, u3=0.f;
        #pragma unroll
        for (int i = 0; i < 17; i++) {
            float e0=__expf(s0[i]-m0), e1=__expf(s1[i]-m1);
            float e2=__expf(s2[i]-m2), e3=__expf(s3[i]-m3);
            s0[i]=e0; s1[i]=e1; s2[i]=e2; s3[i]=e3;
            u0+=e0; u1+=e1; u2+=e2; u3+=e3;
        }
        #pragma unroll
        for (int off = 16; off > 0; off >>= 1) {
            u0 += __shfl_xor_sync(FULL, u0, off);
            u1 += __shfl_xor_sync(FULL, u1, off);
            u2 += __shfl_xor_sync(FULL, u2, off);
            u3 += __shfl_xor_sync(FULL, u3, off);
        }
        float i0=1.f/u0, i1=1.f/u1, i2=1.f/u2, i3=1.f/u3;

        #pragma unroll
        for (int th = 0; th < 2; th++) {
            float o0[8], o1[8], o2[8], o3[8];
            #pragma unroll
            for (int t = 0; t < 8; t++) { o0[t]=0.f; o1[t]=0.f; o2[t]=0.f; o3[t]=0.f; }
            #pragma unroll
            for (int i = 0; i < 17; i++) {
                int j = lane + 32*i;
                if (j < NN) {
                    float w0=s0[i]*i0, w1=s1[i]*i1, w2=s2[i]*i2, w3=s3[i]*i3;
                    #pragma unroll
                    for (int t = 0; t < 8; t++) {
                        float vv = Vs[(th*8 + t)*NP + j];
                        o0[t]+=w0*vv; o1[t]+=w1*vv; o2[t]+=w2*vv; o3[t]+=w3*vv;
                    }
                }
            }
            #pragma unroll
            for (int t = 0; t < 8; t++) {
                #pragma unroll
                for (int off = 16; off > 0; off >>= 1) {
                    o0[t] += __shfl_xor_sync(FULL, o0[t], off);
                    o1[t] += __shfl_xor_sync(FULL, o1[t], off);
                    o2[t] += __shfl_xor_sync(FULL, o2[t], off);
                    o3[t] += __shfl_xor_sync(FULL, o3[t], off);
                }
            }
            if (lane == 0) {
                long base = ((long)(b*NN + q0))*EE + h*DKK + th*8;
                wsplit8(o0, Oh + base,        Ol + base);
                wsplit8(o1, Oh + base + EE,   Ol + base + EE);
                wsplit8(o2, Oh + base + 2*EE, Ol + base + 2*EE);
                wsplit8(o3, Oh + base + 3*EE, Ol + base + 3*EE);
            }
        }
    }
}

// ---------------- instance norm ----------------
__global__ void inorm_stats(const float* __restrict__ Y)
{
    int b = blockIdx.x, ch = blockIdx.y, e = threadIdx.x;
    float s1 = 0.f, s2 = 0.f;
    for (int n = ch; n < NN; n += 8) {
        float v = Y[((long)(b*NN + n))*EE + e];
        s1 += v; s2 += v*v;
    }
    int idx = (b*8 + ch)*EE + e;
    g_part[idx*2]   = s1;
    g_part[idx*2+1] = s2;
}
__global__ void inorm_fin()
{
    int b = blockIdx.x, e = threadIdx.x;
    float s1 = 0.f, s2 = 0.f;
    for (int c = 0; c < 8; c++) {
        int idx = (b*8 + c)*EE + e;
        s1 += g_part[idx*2]; s2 += g_part[idx*2+1];
    }
    float mean = s1 / (float)NN;
    float var  = s2 / (float)NN - mean*mean;
    g_stats[(b*EE+e)*2]   = mean;
    g_stats[(b*EE+e)*2+1] = rsqrtf(var + 1e-5f);
}
__global__ void inorm_apply(const float* __restrict__ Y, const float* __restrict__ gg,
                            const float* __restrict__ bt, float* __restrict__ Xo,
                            bf16* __restrict__ Xh, bf16* __restrict__ Xl)
{
    int idx = blockIdx.x * blockDim.x + threadIdx.x;
    if (idx >= BB*NN*EE) return;
    int e = idx % EE;
    int b = idx / (NN*EE);
    float mean = g_stats[(b*EE+e)*2];
    float istd = g_stats[(b*EE+e)*2+1];
    float v = (Y[idx] - mean) * istd * gg[e] + bt[e];
    Xo[idx] = v;
    split1(v, Xh + idx, Xl + idx);
}

// ---------------- decoder helpers ----------------
__global__ void encmean_kernel()
{
    int b = blockIdx.x, e = threadIdx.x;
    float s = 0.f;
    for (int n = 0; n < NN; n++) s += g_x[((long)(b*NN + n))*EE + e];
    g_encmean[b*EE + e] = s / (float)NN;
}

__global__ void build_cat(const float* __restrict__ loadv, const int* __restrict__ cur,
                          const int* __restrict__ subn, const int* __restrict__ subl,
                          const int* __restrict__ sel)
{
    int r = blockIdx.x;
    int b = r / MM;
    int e = threadIdx.x;
    int c = cur[r];
    float le = g_x[((long)(b*NN + c))*EE + e];

    int len = subl[r];
    const int* nodes = subn + (long)r*LL;
    float ssum = 0.f; int cnt = 0;
    for (int l = 0; l < LL; l++) {
        int nd = nodes[l];
        if (l < len && nd >= DEPOTN) {
            ssum += g_x[((long)(b*NN + nd))*EE + e];
            cnt++;
        }
    }
    float cntf = (cnt > 0) ? (float)cnt : 1.f;
    float smean = ssum / cntf;

    long bl = (long)r*256, br = (long)r*KRT;
    split1(le,    g_catlh + bl + e,       g_catll + bl + e);
    split1(smean, g_catlh + bl + 128 + e, g_catll + bl + 128 + e);
    split1(le,    g_catrh + br + e,       g_catrl + br + e);
    split1(g_encmean[b*EE + e], g_catrh + br + 128 + e, g_catrl + br + 128 + e);
    if (e == 0) split1(loadv[r], g_catrh + br + 256, g_catrl + br + 256);
    if (e >= 1 && e < 32) { g_catrh[br + 256 + e] = __float2bfloat16(0.f);
                            g_catrl[br + 256 + e] = __float2bfloat16(0.f); }
    if (e == 0) {
        int s2 = sel[(long)r*4 + 2];
        g_flag[r] = (s2 >= DEPOTN && c < DEPOTN) ? 1.f : 0.f;
    }
}

__global__ void blend_kernel()
{
    int idx = blockIdx.x * blockDim.x + threadIdx.x;
    if (idx >= BB*MM*EE) return;
    int r = idx / EE;
    float f = g_flag[r];
    g_fq[idx] = f * g_qloc[idx] + (1.f - f) * g_qrout[idx];
}

// ---------------- final tanh-clip + mask + softmax ----------------
__global__ void final_kernel(const float* __restrict__ mask, float* __restrict__ out)
{
    int r = blockIdx.x;
    int tid = threadIdx.x;
    __shared__ float buf[NN];
    __shared__ float red[256];
    const float* sn = g_sn + (long)r*NN;
    const float* mk = mask + (long)r*NN;
    const float invs = 0.08838834764831845f;

    float lm = -1e30f;
    for (int j = tid; j < NN; j += 256) {
        float v = 10.f * tanhf(sn[j] * invs) + mk[j];
        buf[j] = v;
        lm = fmaxf(lm, v);
    }
    red[tid] = lm; __syncthreads();
    for (int off = 128; off > 0; off >>= 1) {
        if (tid < off) red[tid] = fmaxf(red[tid], red[tid+off]);
        __syncthreads();
    }
    float mx = red[0]; __syncthreads();

    float ls = 0.f;
    for (int j = tid; j < NN; j += 256) {
        float e0 = __expf(buf[j] - mx);
        buf[j] = e0; ls += e0;
    }
    red[tid] = ls; __syncthreads();
    for (int off = 128; off > 0; off >>= 1) {
        if (tid < off) red[tid] += red[tid+off];
        __syncthreads();
    }
    float inv = 1.f / red[0];
    for (int j = tid; j < NN; j += 256)
        out[(long)r*NN + j] = buf[j] * inv;
}

// ---------------- host ----------------
#define GEMM_SMEM 81920

static void launch_tc(const bf16* Ah, const bf16* Al, const bf16* Bh, const bf16* Bl,
                      const float* bias, const float* resid,
                      float* C, bf16* Ch, bf16* Cl,
                      int R, int K, int Cout, int batch,
                      long sA, long sB, long sC, int relu)
{
    dim3 grid((R + 127) / 128, (Cout + 127) / 128, batch);
    gemm_tc2<<<grid, 256, GEMM_SMEM>>>(Ah, Al, Bh, Bl, bias, resid, C, Ch, Cl,
                                       R, K, Cout, sA, sB, sC, relu);
}

#define SYM(p, s) cudaGetSymbolAddress((void**)&p, s)

extern "C" void kernel_launch(void* const* d_in, const int* in_sizes, int n_in,
                              void* d_out, int out_size)
{
    const float* depot  = (const float*)d_in[0];
    const float* cust   = (const float*)d_in[1];
    const float* mask   = (const float*)d_in[2];
    const float* loadv  = (const float*)d_in[3];
    const int*   cur    = (const int*)d_in[4];
    const int*   subn   = (const int*)d_in[5];
    const int*   subl   = (const int*)d_in[6];
    const int*   sel    = (const int*)d_in[7];
    const float* edW    = (const float*)d_in[8];
    const float* edb    = (const float*)d_in[9];
    const float* ecW    = (const float*)d_in[10];
    const float* ecb    = (const float*)d_in[11];
    const float* Wq     = (const float*)d_in[12];
    const float* Wk     = (const float*)d_in[13];
    const float* Wv     = (const float*)d_in[14];
    const float* Wc     = (const float*)d_in[15];
    const float* Wcb    = (const float*)d_in[16];
    const float* n1g    = (const float*)d_in[17];
    const float* n1b    = (const float*)d_in[18];
    const float* fW1    = (const float*)d_in[19];
    const float* fb1    = (const float*)d_in[20];
    const float* fW2    = (const float*)d_in[21];
    const float* fb2    = (const float*)d_in[22];
    const float* n2g    = (const float*)d_in[23];
    const float* n2b    = (const float*)d_in[24];
    const float* dWqloc = (const float*)d_in[25];
    const float* dWqrt  = (const float*)d_in[26];
    const float* dWk    = (const float*)d_in[27];
    const float* dWv    = (const float*)d_in[28];
    const float* dWc    = (const float*)d_in[29];
    const float* dWcb   = (const float*)d_in[30];
    float* out = (float*)d_out;

    float *px, *pqkv, *py, *px1, *pkvd, *pqloc, *pqrout, *pfq, *psn;
    SYM(px, g_x); SYM(pqkv, g_qkv); SYM(py, g_y); SYM(px1, g_x1);
    SYM(pkvd, g_kvd); SYM(pqloc, g_qloc); SYM(pqrout, g_qrout);
    SYM(pfq, g_fq); SYM(psn, g_sn);

    bf16 *pxh,*pxl, *px1h,*px1l, *pmhh,*pmhl, *pffhh,*pffhl, *pattnh,*pattnl;
    bf16 *pscoreh,*pscorel, *pcatlh,*pcatll, *pcatrh,*pcatrl;
    bf16 *pwqkvh,*pwqkvl, *pwch,*pwcl, *pf1h,*pf1l, *pf2h,*pf2l;
    bf16 *pwkvh,*pwkvl, *pwqlh,*pwqll, *pwpah,*pwpal, *pwdch,*pwdcl;
    SYM(pxh, g_xh); SYM(pxl, g_xl); SYM(px1h, g_x1h); SYM(px1l, g_x1l);
    SYM(pmhh, g_mhh); SYM(pmhl, g_mhl); SYM(pffhh, g_ffhh); SYM(pffhl, g_ffhl);
    SYM(pattnh, g_attnh); SYM(pattnl, g_attnl);
    SYM(pscoreh, g_scoreh); SYM(pscorel, g_scorel);
    SYM(pcatlh, g_catlh); SYM(pcatll, g_catll); SYM(pcatrh, g_catrh); SYM(pcatrl, g_catrl);
    SYM(pwqkvh, g_wqkvh); SYM(pwqkvl, g_wqkvl); SYM(pwch, g_wch); SYM(pwcl, g_wcl);
    SYM(pf1h, g_f1h); SYM(pf1l, g_f1l); SYM(pf2h, g_f2h); SYM(pf2l, g_f2l);
    SYM(pwkvh, g_wkvh); SYM(pwkvl, g_wkvl); SYM(pwqlh, g_wqlh); SYM(pwqll, g_wqll);
    SYM(pwpah, g_wpah); SYM(pwpal, g_wpal); SYM(pwdch, g_wdch); SYM(pwdcl, g_wdcl);

    const int R = BB * NN;
    const int TOT = BB * NN * EE;
    const int ATTN_SMEM = 2 * DKK * NP * (int)sizeof(float);
    static int smem_set = 0;
    if (!smem_set) {
        cudaFuncSetAttribute(attn3_kernel, cudaFuncAttributeMaxDynamicSharedMemorySize, ATTN_SMEM);
        cudaFuncSetAttribute(gemm_tc2, cudaFuncAttributeMaxDynamicSharedMemorySize, GEMM_SMEM);
        smem_set = 1;
    }

    // ---- one-time converts ----
    embed_kernel<<<(TOT + 255)/256, 256>>>(depot, cust, edW, edb, ecW, ecb);
    pack_w<<<(NLL*384*EE + 256*EE + 255)/256, 256>>>(Wq, Wk, Wv, dWk, dWv);
    padw_kernel<<<(EE*KRT + 255)/256, 256>>>(dWqrt);
    cvt_split<<<(NLL*EE*EE + 255)/256, 256>>>(Wc,  pwch, pwcl, NLL*EE*EE);
    cvt_split<<<(NLL*FFHH*EE + 255)/256, 256>>>(fW1, pf1h, pf1l, NLL*FFHH*EE);
    cvt_split<<<(NLL*EE*FFHH + 255)/256, 256>>>(fW2, pf2h, pf2l, NLL*EE*FFHH);
    cvt_split<<<(EE*256 + 255)/256, 256>>>(dWqloc, pwqlh, pwqll, EE*256);
    cvt_split<<<(EE*EE + 255)/256, 256>>>(dWc, pwdch, pwdcl, EE*EE);

    // ---- encoder ----
    for (int i = 0; i < NLL; i++) {
        launch_tc(pxh, pxl, pwqkvh + (long)i*384*EE, pwqkvl + (long)i*384*EE,
                  0, 0, pqkv, 0, 0, R, EE, 384, 1, 0, 0, 0, 0);
        attn3_kernel<<<dim3(HH, BB), 256, ATTN_SMEM>>>(pqkv, 384, pqkv + 128, 384,
                                                       pqkv + 256, 384, (const float*)0,
                                                       pmhh, pmhl);
        launch_tc(pmhh, pmhl, pwch + (long)i*EE*EE, pwcl + (long)i*EE*EE,
                  Wcb + (long)i*EE, px, py, 0, 0, R, EE, EE, 1, 0, 0, 0, 0);
        inorm_stats<<<dim3(BB, 8), EE>>>(py);
        inorm_fin<<<BB, EE>>>();
        inorm_apply<<<(TOT + 255)/256, 256>>>(py, n1g + (long)i*EE, n1b + (long)i*EE,
                                              px1, px1h, px1l);
        launch_tc(px1h, px1l, pf1h + (long)i*FFHH*EE, pf1l + (long)i*FFHH*EE,
                  fb1 + (long)i*FFHH, 0, 0, pffhh, pffhl, R, EE, FFHH, 1, 0, 0, 0, 1);
        launch_tc(pffhh, pffhl, pf2h + (long)i*EE*FFHH, pf2l + (long)i*EE*FFHH,
                  fb2 + (long)i*EE, px1, py, 0, 0, R, FFHH, EE, 1, 0, 0, 0, 0);
        inorm_stats<<<dim3(BB, 8), EE>>>(py);
        inorm_fin<<<BB, EE>>>();
        inorm_apply<<<(TOT + 255)/256, 256>>>(py, n2g + (long)i*EE, n2b + (long)i*EE,
                                              px, pxh, pxl);
    }

    // ---- decoder ----
    launch_tc(pxh, pxl, pwkvh, pwkvl, 0, 0, pkvd, 0, 0, R, EE, 256, 1, 0, 0, 0, 0);
    encmean_kernel<<<BB, EE>>>();
    build_cat<<<BB*MM, EE>>>(loadv, cur, subn, subl, sel);
    launch_tc(pcatlh, pcatll, pwqlh, pwqll, 0, 0, pqloc, 0, 0, R, 256, EE, 1, 0, 0, 0, 0);
    launch_tc(pcatrh, pcatrl, pwpah, pwpal, 0, 0, pqrout, 0, 0, R, KRT, EE, 1, 0, 0, 0, 0);
    blend_kernel<<<(BB*MM*EE + 255)/256, 256>>>();
    attn3_kernel<<<dim3(HH, BB), 256, ATTN_SMEM>>>(pfq, 128, pkvd, 256, pkvd + 128, 256,
                                                   mask, pattnh, pattnl);
    launch_tc(pattnh, pattnl, pwdch, pwdcl, dWcb, 0, 0, pscoreh, pscorel,
              R, EE, EE, 1, 0, 0, 0, 0);
    launch_tc(pscoreh, pscorel, pxh, pxl, 0, 0, psn, 0, 0, MM, EE, NN, BB,
              (long)MM*EE, (long)NN*EE, (long)MM*NN, 0);
    final_kernel<<<BB*MM, 256>>>(mask, out);
}